// round 1
// baseline (speedup 1.0000x reference)
#include <cuda_runtime.h>
#include <math.h>

#define BB 4
#define NN 10000
#define DD 256
#define EE 160000
#define SS 2
#define NPASS 6
#define HID 80
#define OUTD 10

// ---------------- device scratch (static: no allocations allowed) ----------------
__device__ float g_h  [BB * NN * DD];        // node state
__device__ float g_inc[BB * NN * DD];        // incoming messages
__device__ float g_gi [BB * NN * 3 * DD];    // GRU input gates
__device__ float g_gh [BB * NN * 3 * DD];    // GRU hidden gates
__device__ float g_w1t[SS * DD * DD];        // edge_w1 transposed (s, d, f)
__device__ float g_w2t[SS * DD * DD];
__device__ float g_wiht[DD * 3 * DD];        // gru_w_ih transposed (d, e)
__device__ float g_whht[DD * 3 * DD];
__device__ float g_s  [BB * DD];             // node-sum

// ---------------- generic helpers ----------------
__global__ void copy4(float4* __restrict__ dst, const float4* __restrict__ src, int n4) {
    int i = blockIdx.x * 256 + threadIdx.x;
    if (i < n4) dst[i] = src[i];
}
__global__ void zero4(float4* __restrict__ dst, int n4) {
    int i = blockIdx.x * 256 + threadIdx.x;
    if (i < n4) dst[i] = make_float4(0.f, 0.f, 0.f, 0.f);
}

// transpose all weight matrices (cheap, once per launch)
__global__ void prep_weights(const float* __restrict__ w1, const float* __restrict__ w2,
                             const float* __restrict__ wih, const float* __restrict__ whh) {
    int idx = blockIdx.x * 256 + threadIdx.x;
    if (idx < SS * DD * DD) {
        int s = idx / (DD * DD);
        int r = idx - s * DD * DD;
        int f = r / DD, d = r - f * DD;
        g_w1t[s * DD * DD + d * DD + f] = w1[idx];
        g_w2t[s * DD * DD + d * DD + f] = w2[idx];
    }
    if (idx < 3 * DD * DD) {
        int e = idx / DD, d = idx - e * DD;
        g_wiht[d * (3 * DD) + e] = wih[idx];
        g_whht[d * (3 * DD) + e] = whh[idx];
    }
}

// ---------------- core GEMM accumulate: C_tile(64x256) += A(64x256) * Wt(256 x Nw slice) ----
// As: smem [64][256]; Ws: smem [32][256] staging; Wt global in (k, col) layout.
// Thread (tx=tid&15, ty=tid>>4) owns rows m=ty+16i (i<4), cols tx*4+k+64j (j<4,k<4).
__device__ __forceinline__ void gemm_acc(
    const float* As, float* Ws,
    const float* __restrict__ Wt, int ldw, int col0,
    float acc[4][16], int tx, int ty, int tid)
{
#pragma unroll
    for (int i = 0; i < 4; ++i)
#pragma unroll
        for (int j = 0; j < 16; ++j) acc[i][j] = 0.f;

    for (int kc = 0; kc < 8; ++kc) {
        __syncthreads();
#pragma unroll
        for (int it = 0; it < 8; ++it) {
            int q  = it * 256 + tid;     // float4 index into Ws
            int r  = q >> 6;             // k-row within chunk (0..31)
            int c4 = q & 63;             // float4 column
            ((float4*)Ws)[q] = *(const float4*)(Wt + (size_t)(kc * 32 + r) * ldw + col0 + c4 * 4);
        }
        __syncthreads();
#pragma unroll 4
        for (int d = 0; d < 32; ++d) {
            int kd = kc * 32 + d;
            float a0 = As[(ty +  0) * DD + kd];
            float a1 = As[(ty + 16) * DD + kd];
            float a2 = As[(ty + 32) * DD + kd];
            float a3 = As[(ty + 48) * DD + kd];
#pragma unroll
            for (int j = 0; j < 4; ++j) {
                float4 w = *(const float4*)(Ws + d * DD + tx * 4 + 64 * j);
                acc[0][j*4+0] += a0 * w.x; acc[0][j*4+1] += a0 * w.y; acc[0][j*4+2] += a0 * w.z; acc[0][j*4+3] += a0 * w.w;
                acc[1][j*4+0] += a1 * w.x; acc[1][j*4+1] += a1 * w.y; acc[1][j*4+2] += a1 * w.z; acc[1][j*4+3] += a1 * w.w;
                acc[2][j*4+0] += a2 * w.x; acc[2][j*4+1] += a2 * w.y; acc[2][j*4+2] += a2 * w.z; acc[2][j*4+3] += a2 * w.w;
                acc[3][j*4+0] += a3 * w.x; acc[3][j*4+1] += a3 * w.y; acc[3][j*4+2] += a3 * w.z; acc[3][j*4+3] += a3 * w.w;
            }
        }
    }
}

// ---------------- fused edge MLP: gather -> GEMM1+leaky -> GEMM2 -> atomic scatter ----------
__global__ void __launch_bounds__(256, 1) edge_fused(
    const int* __restrict__ edges,
    const float* __restrict__ eb1,
    const float* __restrict__ eb2)
{
    extern __shared__ float sm[];
    float* As = sm;                 // 64*256
    float* C1 = sm + 64 * DD;       // 64*256
    float* Ws = sm + 128 * DD;      // 32*256
    __shared__ int s_dst[64];
    __shared__ int s_src[64];

    int tid = threadIdx.x;
    int tx = tid & 15, ty = tid >> 4;
    int b = blockIdx.y, si = blockIdx.z;
    int e0 = blockIdx.x * 64;

    const int* eb = edges + (((size_t)b * SS + si) * EE + e0) * 2;
    if (tid < 64) { s_dst[tid] = eb[tid * 2]; s_src[tid] = eb[tid * 2 + 1]; }
    __syncthreads();

    // gather: 4 threads per edge row, 16 float4 each
    {
        int r = tid >> 2, qq = tid & 3;
        const float4* srcp = (const float4*)(g_h + ((size_t)b * NN + s_src[r]) * DD) + qq * 16;
        float4* dstp = (float4*)(As + r * DD) + qq * 16;
#pragma unroll
        for (int i = 0; i < 16; ++i) dstp[i] = srcp[i];
    }

    float acc[4][16];
    const float* w1ts = g_w1t + si * DD * DD;
    const float* w2ts = g_w2t + si * DD * DD;
    const float* b1s  = eb1 + si * DD;
    const float* b2s  = eb2 + si * DD;

    // GEMM1 + bias + leaky -> C1 (smem)
    gemm_acc(As, Ws, w1ts, DD, 0, acc, tx, ty, tid);
#pragma unroll
    for (int i = 0; i < 4; ++i) {
        int m = ty + 16 * i;
#pragma unroll
        for (int j = 0; j < 4; ++j) {
            int cb = tx * 4 + 64 * j;
            float4 bv = *(const float4*)(b1s + cb);
            float4 v;
            v.x = acc[i][j*4+0] + bv.x; v.y = acc[i][j*4+1] + bv.y;
            v.z = acc[i][j*4+2] + bv.z; v.w = acc[i][j*4+3] + bv.w;
            v.x = v.x > 0.f ? v.x : 0.01f * v.x;
            v.y = v.y > 0.f ? v.y : 0.01f * v.y;
            v.z = v.z > 0.f ? v.z : 0.01f * v.z;
            v.w = v.w > 0.f ? v.w : 0.01f * v.w;
            *(float4*)(C1 + m * DD + cb) = v;
        }
    }

    // GEMM2 + bias -> atomicAdd scatter
    gemm_acc(C1, Ws, w2ts, DD, 0, acc, tx, ty, tid);
#pragma unroll
    for (int i = 0; i < 4; ++i) {
        int m = ty + 16 * i;
        float* dst = g_inc + ((size_t)b * NN + s_dst[m]) * DD;
#pragma unroll
        for (int j = 0; j < 4; ++j) {
            int cb = tx * 4 + 64 * j;
            float4 bv = *(const float4*)(b2s + cb);
            atomicAdd(dst + cb + 0, acc[i][j*4+0] + bv.x);
            atomicAdd(dst + cb + 1, acc[i][j*4+1] + bv.y);
            atomicAdd(dst + cb + 2, acc[i][j*4+2] + bv.z);
            atomicAdd(dst + cb + 3, acc[i][j*4+3] + bv.w);
        }
    }
}

// ---------------- GRU GEMM: C[M x (col tile 256)] = A[M x 256] * Wt + bias ----------------
__global__ void __launch_bounds__(256, 1) sgemm_k256(
    const float* __restrict__ A, const float* __restrict__ Wt,
    const float* __restrict__ bias, float* __restrict__ C, int Nw)
{
    extern __shared__ float sm[];
    float* As = sm;            // 64*256
    float* Ws = sm + 64 * DD;  // 32*256
    int tid = threadIdx.x;
    int tx = tid & 15, ty = tid >> 4;
    size_t row0 = (size_t)blockIdx.x * 64;
    int col0 = blockIdx.y * 256;

    const float4* A4 = (const float4*)(A + row0 * DD);
    float4* As4 = (float4*)As;
#pragma unroll
    for (int it = 0; it < 16; ++it) As4[it * 256 + tid] = A4[it * 256 + tid];

    float acc[4][16];
    gemm_acc(As, Ws, Wt, Nw, col0, acc, tx, ty, tid);

#pragma unroll
    for (int i = 0; i < 4; ++i) {
        size_t row = row0 + ty + 16 * i;
#pragma unroll
        for (int j = 0; j < 4; ++j) {
            int cb = tx * 4 + 64 * j;
            float4 bv = *(const float4*)(bias + col0 + cb);
            float4 v;
            v.x = acc[i][j*4+0] + bv.x; v.y = acc[i][j*4+1] + bv.y;
            v.z = acc[i][j*4+2] + bv.z; v.w = acc[i][j*4+3] + bv.w;
            *(float4*)(C + row * Nw + col0 + cb) = v;
        }
    }
}

// ---------------- GRU pointwise gates (in-place h update) ----------------
__global__ void gru_gate(const float* __restrict__ gi, const float* __restrict__ gh) {
    size_t idx = (size_t)blockIdx.x * 256 + threadIdx.x;   // over B*N*D
    size_t row = idx >> 8;
    int d = (int)(idx & 255);
    const float* gir = gi + row * 768;
    const float* ghr = gh + row * 768;
    float ir = gir[d], iz = gir[256 + d], in_ = gir[512 + d];
    float hr = ghr[d], hz = ghr[256 + d], hn  = ghr[512 + d];
    float r = 1.f / (1.f + expf(-(ir + hr)));
    float z = 1.f / (1.f + expf(-(iz + hz)));
    float n = tanhf(in_ + r * hn);
    float hv = g_h[idx];
    g_h[idx] = (1.f - z) * n + z * hv;
}

// ---------------- node sum over N ----------------
__global__ void node_sum() {
    int b = blockIdx.x, chunk = blockIdx.y;   // 40 chunks of 250 nodes
    int d = threadIdx.x;
    const float* base = g_h + ((size_t)b * NN + chunk * 250) * DD + d;
    float acc = 0.f;
    for (int n = 0; n < 250; ++n) acc += base[(size_t)n * DD];
    atomicAdd(&g_s[b * DD + d], acc);
}

// ---------------- head: log / nan / relu / inf->finite_max, then 3 FC layers ----------------
__global__ void head_kernel(const float* __restrict__ ptype,
                            const float* __restrict__ fc1w, const float* __restrict__ fc1b,
                            const float* __restrict__ fc2w, const float* __restrict__ fc2b,
                            const float* __restrict__ fc3w, const float* __restrict__ fc3b,
                            float* __restrict__ out)
{
    int b = blockIdx.x, tid = threadIdx.x;  // 256 threads
    __shared__ float xs[257];
    __shared__ float red[256];
    __shared__ float a1[HID], a2[HID];

    float sv = g_s[b * DD + tid];
    float l = logf(sv);
    if (isnan(l)) l = 0.f;
    l = fmaxf(l, 0.f);                       // relu (also maps -inf -> 0)
    float fm = isinf(l) ? -INFINITY : l;
    red[tid] = fm;
    __syncthreads();
    for (int off = 128; off > 0; off >>= 1) {
        if (tid < off) red[tid] = fmaxf(red[tid], red[tid + off]);
        __syncthreads();
    }
    float fmax = red[0];
    if (isinf(l)) l = fmax;
    xs[tid] = l;
    if (tid == 0) xs[256] = ptype[b];
    __syncthreads();

    if (tid < HID) {
        float acc = fc1b[tid];
        for (int k = 0; k < 257; ++k) acc += fc1w[tid * 257 + k] * xs[k];
        a1[tid] = acc > 0.f ? acc : 0.01f * acc;
    }
    __syncthreads();
    if (tid < HID) {
        float acc = fc2b[tid];
        for (int k = 0; k < HID; ++k) acc += fc2w[tid * HID + k] * a1[k];
        a2[tid] = acc > 0.f ? acc : 0.01f * acc;
    }
    __syncthreads();
    if (tid < OUTD) {
        float acc = fc3b[tid];
        for (int k = 0; k < HID; ++k) acc += fc3w[tid * HID + k] * a2[k];
        out[b * OUTD + tid] = acc;
    }
}

// ---------------- launch ----------------
extern "C" void kernel_launch(void* const* d_in, const int* in_sizes, int n_in,
                              void* d_out, int out_size) {
    const float* nodes = (const float*)d_in[0];
    const int*   edges = (const int*)  d_in[1];
    const float* ptype = (const float*)d_in[2];
    const float* w_ih  = (const float*)d_in[3];
    const float* w_hh  = (const float*)d_in[4];
    const float* b_ih  = (const float*)d_in[5];
    const float* b_hh  = (const float*)d_in[6];
    const float* ew1   = (const float*)d_in[7];
    const float* eb1   = (const float*)d_in[8];
    const float* ew2   = (const float*)d_in[9];
    const float* eb2   = (const float*)d_in[10];
    const float* fc1w  = (const float*)d_in[11];
    const float* fc1b  = (const float*)d_in[12];
    const float* fc2w  = (const float*)d_in[13];
    const float* fc2b  = (const float*)d_in[14];
    const float* fc3w  = (const float*)d_in[15];
    const float* fc3b  = (const float*)d_in[16];
    float* out = (float*)d_out;

    float *p_h, *p_inc, *p_gi, *p_gh, *p_wiht, *p_whht, *p_s;
    cudaGetSymbolAddress((void**)&p_h,    g_h);
    cudaGetSymbolAddress((void**)&p_inc,  g_inc);
    cudaGetSymbolAddress((void**)&p_gi,   g_gi);
    cudaGetSymbolAddress((void**)&p_gh,   g_gh);
    cudaGetSymbolAddress((void**)&p_wiht, g_wiht);
    cudaGetSymbolAddress((void**)&p_whht, g_whht);
    cudaGetSymbolAddress((void**)&p_s,    g_s);

    const int EDGE_SMEM  = (64 * DD + 64 * DD + 32 * DD) * 4;  // 163840
    const int GEMM_SMEM  = (64 * DD + 32 * DD) * 4;            // 98304
    cudaFuncSetAttribute(edge_fused, cudaFuncAttributeMaxDynamicSharedMemorySize, EDGE_SMEM);
    cudaFuncSetAttribute(sgemm_k256, cudaFuncAttributeMaxDynamicSharedMemorySize, GEMM_SMEM);

    const int n4_state = BB * NN * DD / 4;   // 2,560,000 float4

    // h = nodes
    copy4<<<(n4_state + 255) / 256, 256>>>((float4*)p_h, (const float4*)nodes, n4_state);
    // transpose weights
    prep_weights<<<768, 256>>>(ew1, ew2, w_ih, w_hh);

    for (int j = 0; j < NPASS; ++j) {
        zero4<<<(n4_state + 255) / 256, 256>>>((float4*)p_inc, n4_state);
        edge_fused<<<dim3(EE / 64, BB, SS), 256, EDGE_SMEM>>>(edges, eb1, eb2);
        sgemm_k256<<<dim3(BB * NN / 64, 3), 256, GEMM_SMEM>>>(p_inc, p_wiht, b_ih, p_gi, 3 * DD);
        sgemm_k256<<<dim3(BB * NN / 64, 3), 256, GEMM_SMEM>>>(p_h,   p_whht, b_hh, p_gh, 3 * DD);
        gru_gate<<<BB * NN * DD / 256, 256>>>(p_gi, p_gh);
    }

    zero4<<<1, 256>>>((float4*)p_s, BB * DD / 4);
    node_sum<<<dim3(BB, 40), 256>>>();
    head_kernel<<<BB, 256>>>(ptype, fc1w, fc1b, fc2w, fc2b, fc3w, fc3b, out);
}

// round 2
// speedup vs baseline: 1.0004x; 1.0004x over previous
#include <cuda_runtime.h>
#include <math.h>

#define BB 4
#define NN 10000
#define DD 256
#define EE 160000
#define SS 2
#define NPASS 6
#define HID 80
#define OUTD 10

// ---------------- device scratch (static: no allocations allowed) ----------------
__device__ float g_h  [BB * NN * DD];        // node state
__device__ float g_inc[BB * NN * DD];        // incoming messages
__device__ float g_gi [BB * NN * 3 * DD];    // GRU input gates
__device__ float g_gh [BB * NN * 3 * DD];    // GRU hidden gates
__device__ float g_w1t[SS * DD * DD];        // edge_w1 transposed (s, d, f)
__device__ float g_w2t[SS * DD * DD];
__device__ float g_wiht[DD * 3 * DD];        // gru_w_ih transposed (d, e)
__device__ float g_whht[DD * 3 * DD];
__device__ float g_s  [BB * DD];             // node-sum

// ---------------- generic helpers ----------------
__global__ void copy4(float4* __restrict__ dst, const float4* __restrict__ src, int n4) {
    int i = blockIdx.x * 256 + threadIdx.x;
    if (i < n4) dst[i] = src[i];
}
__global__ void zero4(float4* __restrict__ dst, int n4) {
    int i = blockIdx.x * 256 + threadIdx.x;
    if (i < n4) dst[i] = make_float4(0.f, 0.f, 0.f, 0.f);
}

// transpose all weight matrices (cheap, once per launch)
__global__ void prep_weights(const float* __restrict__ w1, const float* __restrict__ w2,
                             const float* __restrict__ wih, const float* __restrict__ whh) {
    int idx = blockIdx.x * 256 + threadIdx.x;
    if (idx < SS * DD * DD) {
        int s = idx / (DD * DD);
        int r = idx - s * DD * DD;
        int f = r / DD, d = r - f * DD;
        g_w1t[s * DD * DD + d * DD + f] = w1[idx];
        g_w2t[s * DD * DD + d * DD + f] = w2[idx];
    }
    if (idx < 3 * DD * DD) {
        int e = idx / DD, d = idx - e * DD;
        g_wiht[d * (3 * DD) + e] = wih[idx];
        g_whht[d * (3 * DD) + e] = whh[idx];
    }
}

// ---------------- core GEMM accumulate: C_tile(64x256) += A(64x256) * Wt(256 x Nw slice) ----
// As: smem [64][256]; Ws: smem [32][256] staging; Wt global in (k, col) layout.
// Thread (tx=tid&15, ty=tid>>4) owns rows m=ty+16i (i<4), cols tx*4+k+64j (j<4,k<4).
__device__ __forceinline__ void gemm_acc(
    const float* As, float* Ws,
    const float* __restrict__ Wt, int ldw, int col0,
    float acc[4][16], int tx, int ty, int tid)
{
#pragma unroll
    for (int i = 0; i < 4; ++i)
#pragma unroll
        for (int j = 0; j < 16; ++j) acc[i][j] = 0.f;

    for (int kc = 0; kc < 8; ++kc) {
        __syncthreads();
#pragma unroll
        for (int it = 0; it < 8; ++it) {
            int q  = it * 256 + tid;     // float4 index into Ws
            int r  = q >> 6;             // k-row within chunk (0..31)
            int c4 = q & 63;             // float4 column
            ((float4*)Ws)[q] = *(const float4*)(Wt + (size_t)(kc * 32 + r) * ldw + col0 + c4 * 4);
        }
        __syncthreads();
#pragma unroll 4
        for (int d = 0; d < 32; ++d) {
            int kd = kc * 32 + d;
            float a0 = As[(ty +  0) * DD + kd];
            float a1 = As[(ty + 16) * DD + kd];
            float a2 = As[(ty + 32) * DD + kd];
            float a3 = As[(ty + 48) * DD + kd];
#pragma unroll
            for (int j = 0; j < 4; ++j) {
                float4 w = *(const float4*)(Ws + d * DD + tx * 4 + 64 * j);
                acc[0][j*4+0] += a0 * w.x; acc[0][j*4+1] += a0 * w.y; acc[0][j*4+2] += a0 * w.z; acc[0][j*4+3] += a0 * w.w;
                acc[1][j*4+0] += a1 * w.x; acc[1][j*4+1] += a1 * w.y; acc[1][j*4+2] += a1 * w.z; acc[1][j*4+3] += a1 * w.w;
                acc[2][j*4+0] += a2 * w.x; acc[2][j*4+1] += a2 * w.y; acc[2][j*4+2] += a2 * w.z; acc[2][j*4+3] += a2 * w.w;
                acc[3][j*4+0] += a3 * w.x; acc[3][j*4+1] += a3 * w.y; acc[3][j*4+2] += a3 * w.z; acc[3][j*4+3] += a3 * w.w;
            }
        }
    }
}

// ---------------- fused edge MLP: gather -> GEMM1+leaky -> GEMM2 -> atomic scatter ----------
__global__ void __launch_bounds__(256, 1) edge_fused(
    const int* __restrict__ edges,
    const float* __restrict__ eb1,
    const float* __restrict__ eb2)
{
    extern __shared__ float sm[];
    float* As = sm;                 // 64*256
    float* C1 = sm + 64 * DD;       // 64*256
    float* Ws = sm + 128 * DD;      // 32*256
    __shared__ int s_dst[64];
    __shared__ int s_src[64];

    int tid = threadIdx.x;
    int tx = tid & 15, ty = tid >> 4;
    int b = blockIdx.y, si = blockIdx.z;
    int e0 = blockIdx.x * 64;

    const int* eb = edges + (((size_t)b * SS + si) * EE + e0) * 2;
    if (tid < 64) { s_dst[tid] = eb[tid * 2]; s_src[tid] = eb[tid * 2 + 1]; }
    __syncthreads();

    // gather: 4 threads per edge row, 16 float4 each
    {
        int r = tid >> 2, qq = tid & 3;
        const float4* srcp = (const float4*)(g_h + ((size_t)b * NN + s_src[r]) * DD) + qq * 16;
        float4* dstp = (float4*)(As + r * DD) + qq * 16;
#pragma unroll
        for (int i = 0; i < 16; ++i) dstp[i] = srcp[i];
    }

    float acc[4][16];
    const float* w1ts = g_w1t + si * DD * DD;
    const float* w2ts = g_w2t + si * DD * DD;
    const float* b1s  = eb1 + si * DD;
    const float* b2s  = eb2 + si * DD;

    // GEMM1 + bias + leaky -> C1 (smem)
    gemm_acc(As, Ws, w1ts, DD, 0, acc, tx, ty, tid);
#pragma unroll
    for (int i = 0; i < 4; ++i) {
        int m = ty + 16 * i;
#pragma unroll
        for (int j = 0; j < 4; ++j) {
            int cb = tx * 4 + 64 * j;
            float4 bv = *(const float4*)(b1s + cb);
            float4 v;
            v.x = acc[i][j*4+0] + bv.x; v.y = acc[i][j*4+1] + bv.y;
            v.z = acc[i][j*4+2] + bv.z; v.w = acc[i][j*4+3] + bv.w;
            v.x = v.x > 0.f ? v.x : 0.01f * v.x;
            v.y = v.y > 0.f ? v.y : 0.01f * v.y;
            v.z = v.z > 0.f ? v.z : 0.01f * v.z;
            v.w = v.w > 0.f ? v.w : 0.01f * v.w;
            *(float4*)(C1 + m * DD + cb) = v;
        }
    }

    // GEMM2 + bias -> atomicAdd scatter
    gemm_acc(C1, Ws, w2ts, DD, 0, acc, tx, ty, tid);
#pragma unroll
    for (int i = 0; i < 4; ++i) {
        int m = ty + 16 * i;
        float* dst = g_inc + ((size_t)b * NN + s_dst[m]) * DD;
#pragma unroll
        for (int j = 0; j < 4; ++j) {
            int cb = tx * 4 + 64 * j;
            float4 bv = *(const float4*)(b2s + cb);
            atomicAdd(dst + cb + 0, acc[i][j*4+0] + bv.x);
            atomicAdd(dst + cb + 1, acc[i][j*4+1] + bv.y);
            atomicAdd(dst + cb + 2, acc[i][j*4+2] + bv.z);
            atomicAdd(dst + cb + 3, acc[i][j*4+3] + bv.w);
        }
    }
}

// ---------------- GRU GEMM: C[M x (col tile 256)] = A[M x 256] * Wt + bias ----------------
__global__ void __launch_bounds__(256, 1) sgemm_k256(
    const float* __restrict__ A, const float* __restrict__ Wt,
    const float* __restrict__ bias, float* __restrict__ C, int Nw)
{
    extern __shared__ float sm[];
    float* As = sm;            // 64*256
    float* Ws = sm + 64 * DD;  // 32*256
    int tid = threadIdx.x;
    int tx = tid & 15, ty = tid >> 4;
    size_t row0 = (size_t)blockIdx.x * 64;
    int col0 = blockIdx.y * 256;

    const float4* A4 = (const float4*)(A + row0 * DD);
    float4* As4 = (float4*)As;
#pragma unroll
    for (int it = 0; it < 16; ++it) As4[it * 256 + tid] = A4[it * 256 + tid];

    float acc[4][16];
    gemm_acc(As, Ws, Wt, Nw, col0, acc, tx, ty, tid);

#pragma unroll
    for (int i = 0; i < 4; ++i) {
        size_t row = row0 + ty + 16 * i;
#pragma unroll
        for (int j = 0; j < 4; ++j) {
            int cb = tx * 4 + 64 * j;
            float4 bv = *(const float4*)(bias + col0 + cb);
            float4 v;
            v.x = acc[i][j*4+0] + bv.x; v.y = acc[i][j*4+1] + bv.y;
            v.z = acc[i][j*4+2] + bv.z; v.w = acc[i][j*4+3] + bv.w;
            *(float4*)(C + row * Nw + col0 + cb) = v;
        }
    }
}

// ---------------- GRU pointwise gates (in-place h update) ----------------
__global__ void gru_gate(const float* __restrict__ gi, const float* __restrict__ gh) {
    size_t idx = (size_t)blockIdx.x * 256 + threadIdx.x;   // over B*N*D
    size_t row = idx >> 8;
    int d = (int)(idx & 255);
    const float* gir = gi + row * 768;
    const float* ghr = gh + row * 768;
    float ir = gir[d], iz = gir[256 + d], in_ = gir[512 + d];
    float hr = ghr[d], hz = ghr[256 + d], hn  = ghr[512 + d];
    float r = 1.f / (1.f + expf(-(ir + hr)));
    float z = 1.f / (1.f + expf(-(iz + hz)));
    float n = tanhf(in_ + r * hn);
    float hv = g_h[idx];
    g_h[idx] = (1.f - z) * n + z * hv;
}

// ---------------- node sum over N ----------------
__global__ void node_sum() {
    int b = blockIdx.x, chunk = blockIdx.y;   // 40 chunks of 250 nodes
    int d = threadIdx.x;
    const float* base = g_h + ((size_t)b * NN + chunk * 250) * DD + d;
    float acc = 0.f;
    for (int n = 0; n < 250; ++n) acc += base[(size_t)n * DD];
    atomicAdd(&g_s[b * DD + d], acc);
}

// ---------------- head: log / nan / relu / inf->finite_max, then 3 FC layers ----------------
__global__ void head_kernel(const float* __restrict__ ptype,
                            const float* __restrict__ fc1w, const float* __restrict__ fc1b,
                            const float* __restrict__ fc2w, const float* __restrict__ fc2b,
                            const float* __restrict__ fc3w, const float* __restrict__ fc3b,
                            float* __restrict__ out)
{
    int b = blockIdx.x, tid = threadIdx.x;  // 256 threads
    __shared__ float xs[257];
    __shared__ float red[256];
    __shared__ float a1[HID], a2[HID];

    float sv = g_s[b * DD + tid];
    float l = logf(sv);
    if (isnan(l)) l = 0.f;
    l = fmaxf(l, 0.f);                       // relu (also maps -inf -> 0)
    float fm = isinf(l) ? -INFINITY : l;
    red[tid] = fm;
    __syncthreads();
    for (int off = 128; off > 0; off >>= 1) {
        if (tid < off) red[tid] = fmaxf(red[tid], red[tid + off]);
        __syncthreads();
    }
    float fmax = red[0];
    if (isinf(l)) l = fmax;
    xs[tid] = l;
    if (tid == 0) xs[256] = ptype[b];
    __syncthreads();

    if (tid < HID) {
        float acc = fc1b[tid];
        for (int k = 0; k < 257; ++k) acc += fc1w[tid * 257 + k] * xs[k];
        a1[tid] = acc > 0.f ? acc : 0.01f * acc;
    }
    __syncthreads();
    if (tid < HID) {
        float acc = fc2b[tid];
        for (int k = 0; k < HID; ++k) acc += fc2w[tid * HID + k] * a1[k];
        a2[tid] = acc > 0.f ? acc : 0.01f * acc;
    }
    __syncthreads();
    if (tid < OUTD) {
        float acc = fc3b[tid];
        for (int k = 0; k < HID; ++k) acc += fc3w[tid * HID + k] * a2[k];
        out[b * OUTD + tid] = acc;
    }
}

// ---------------- launch ----------------
extern "C" void kernel_launch(void* const* d_in, const int* in_sizes, int n_in,
                              void* d_out, int out_size) {
    const float* nodes = (const float*)d_in[0];
    const int*   edges = (const int*)  d_in[1];
    const float* ptype = (const float*)d_in[2];
    const float* w_ih  = (const float*)d_in[3];
    const float* w_hh  = (const float*)d_in[4];
    const float* b_ih  = (const float*)d_in[5];
    const float* b_hh  = (const float*)d_in[6];
    const float* ew1   = (const float*)d_in[7];
    const float* eb1   = (const float*)d_in[8];
    const float* ew2   = (const float*)d_in[9];
    const float* eb2   = (const float*)d_in[10];
    const float* fc1w  = (const float*)d_in[11];
    const float* fc1b  = (const float*)d_in[12];
    const float* fc2w  = (const float*)d_in[13];
    const float* fc2b  = (const float*)d_in[14];
    const float* fc3w  = (const float*)d_in[15];
    const float* fc3b  = (const float*)d_in[16];
    float* out = (float*)d_out;

    float *p_h, *p_inc, *p_gi, *p_gh, *p_wiht, *p_whht, *p_s;
    cudaGetSymbolAddress((void**)&p_h,    g_h);
    cudaGetSymbolAddress((void**)&p_inc,  g_inc);
    cudaGetSymbolAddress((void**)&p_gi,   g_gi);
    cudaGetSymbolAddress((void**)&p_gh,   g_gh);
    cudaGetSymbolAddress((void**)&p_wiht, g_wiht);
    cudaGetSymbolAddress((void**)&p_whht, g_whht);
    cudaGetSymbolAddress((void**)&p_s,    g_s);

    const int EDGE_SMEM  = (64 * DD + 64 * DD + 32 * DD) * 4;  // 163840
    const int GEMM_SMEM  = (64 * DD + 32 * DD) * 4;            // 98304
    cudaFuncSetAttribute(edge_fused, cudaFuncAttributeMaxDynamicSharedMemorySize, EDGE_SMEM);
    cudaFuncSetAttribute(sgemm_k256, cudaFuncAttributeMaxDynamicSharedMemorySize, GEMM_SMEM);

    const int n4_state = BB * NN * DD / 4;   // 2,560,000 float4

    // h = nodes
    copy4<<<(n4_state + 255) / 256, 256>>>((float4*)p_h, (const float4*)nodes, n4_state);
    // transpose weights
    prep_weights<<<768, 256>>>(ew1, ew2, w_ih, w_hh);

    for (int j = 0; j < NPASS; ++j) {
        zero4<<<(n4_state + 255) / 256, 256>>>((float4*)p_inc, n4_state);
        edge_fused<<<dim3(EE / 64, BB, SS), 256, EDGE_SMEM>>>(edges, eb1, eb2);
        sgemm_k256<<<dim3(BB * NN / 64, 3), 256, GEMM_SMEM>>>(p_inc, p_wiht, b_ih, p_gi, 3 * DD);
        sgemm_k256<<<dim3(BB * NN / 64, 3), 256, GEMM_SMEM>>>(p_h,   p_whht, b_hh, p_gh, 3 * DD);
        gru_gate<<<BB * NN * DD / 256, 256>>>(p_gi, p_gh);
    }

    zero4<<<1, 256>>>((float4*)p_s, BB * DD / 4);
    node_sum<<<dim3(BB, 40), 256>>>();
    head_kernel<<<BB, 256>>>(ptype, fc1w, fc1b, fc2w, fc2b, fc3w, fc3b, out);
}

// round 5
// speedup vs baseline: 2.8954x; 2.8943x over previous
#include <cuda_runtime.h>
#include <cuda_bf16.h>
#include <math.h>

#define BB 4
#define NN 10000
#define DD 256
#define EE 160000
#define SS 2
#define NPASS 6
#define HID 80
#define OUTD 10
#define MROWS (BB * NN)   // 40000

// ---------------- device scratch ----------------
__device__ float g_h  [BB * NN * DD];
__device__ float g_inc[BB * NN * DD];
__device__ float g_gi [BB * NN * 3 * DD];
__device__ float g_gh [BB * NN * 3 * DD];
__device__ float g_s  [BB * DD];
// edge weights: [stage][si][chunk8][hi/lo][n256][16 words] (32-bit words, XOR-swizzled)
__device__ __align__(16) unsigned g_ewt[2][SS][8][2][256][16];
// gru weights: [which][nslice3][chunk8][hi/lo][n256][16 words]
__device__ __align__(16) unsigned g_gwt[2][3][8][2][256][16];

// ---------------- PTX helpers (sm_103-safe subset: bulk-copy, mbarrier, HMMA) ----
__device__ __forceinline__ unsigned smem_u32(const void* p) {
    unsigned a;
    asm("{ .reg .u64 t; cvta.to.shared.u64 t, %1; cvt.u32.u64 %0, t; }" : "=r"(a) : "l"(p));
    return a;
}
#define MB_INIT(mb, c) asm volatile("mbarrier.init.shared.b64 [%0], %1;" :: "r"(mb), "r"(c) : "memory")
#define MB_EXPECT(mb, n) asm volatile("mbarrier.arrive.expect_tx.shared.b64 _, [%0], %1;" :: "r"(mb), "r"(n) : "memory")
#define MB_WAIT(mb, ph) do { \
    unsigned _m = (mb), _p = (ph), _d; \
    asm volatile("{\n\t.reg .pred p;\n\t" \
        "mbarrier.try_wait.parity.acquire.cta.shared::cta.b64 p, [%1], %2;\n\t" \
        "selp.b32 %0, 1, 0, p;\n\t}" : "=r"(_d) : "r"(_m), "r"(_p) : "memory"); \
    if (!_d) { \
        asm volatile("{\n\t.reg .pred P1;\n\tWL_%=:\n\t" \
            "mbarrier.try_wait.parity.acquire.cta.shared::cta.b64 P1, [%0], %1, 0x989680;\n\t" \
            "@P1 bra.uni WD_%=;\n\tbra.uni WL_%=;\n\tWD_%=:\n\t}" :: "r"(_m), "r"(_p) : "memory"); \
    } \
} while (0)
__device__ __forceinline__ void bulk_g2s(unsigned dst, const void* src, unsigned bytes, unsigned mbar) {
    asm volatile("cp.async.bulk.shared::cluster.global.mbarrier::complete_tx::bytes [%0], [%1], %2, [%3];"
        :: "r"(dst), "l"(src), "r"(bytes), "r"(mbar) : "memory");
}
__device__ __forceinline__ void mma16816(float c[4], unsigned a0, unsigned a1, unsigned a2, unsigned a3,
                                         unsigned b0, unsigned b1) {
    asm volatile("mma.sync.aligned.m16n8k16.row.col.f32.bf16.bf16.f32 "
        "{%0,%1,%2,%3}, {%4,%5,%6,%7}, {%8,%9}, {%0,%1,%2,%3};"
        : "+f"(c[0]), "+f"(c[1]), "+f"(c[2]), "+f"(c[3])
        : "r"(a0), "r"(a1), "r"(a2), "r"(a3), "r"(b0), "r"(b1));
}
__device__ __forceinline__ unsigned pack2(float a, float b) {
    __nv_bfloat162 t = __floats2bfloat162_rn(a, b);
    return *(unsigned*)&t;
}

// ---------------- smem layout (bytes), shared by edge + gru kernels ----------------
#define AW_PITCH 132
#define OFF_ALO_W 16896          /* words */
#define OFF_W_B   135168
#define OFF_W_W   33792          /* words */
#define OFF_DST_B 200704
#define OFF_SRC_B 201216
#define OFF_BAR_B 201728
#define TSMEM     201760

// ---------------- helpers ----------------
__global__ void copy4(float4* __restrict__ dst, const float4* __restrict__ src, int n4) {
    int i = blockIdx.x * 256 + threadIdx.x;
    if (i < n4) dst[i] = src[i];
}
__global__ void zero4(float4* __restrict__ dst, int n4) {
    int i = blockIdx.x * 256 + threadIdx.x;
    if (i < n4) dst[i] = make_float4(0.f, 0.f, 0.f, 0.f);
}

// bake weights: bf16 hi/lo, swizzled word layout w' = w ^ (((n>>1)&3)<<2)
__global__ void prep_weights(const float* __restrict__ w1, const float* __restrict__ w2,
                             const float* __restrict__ wih, const float* __restrict__ whh) {
    int idx = blockIdx.x * 256 + threadIdx.x;   // 0 .. 393215
    if (idx < 2 * SS * 256 * 256) {             // edge weights: 262144
        int k  = idx & 255;
        int n  = (idx >> 8) & 255;
        int si = (idx >> 16) & 1;
        int st = idx >> 17;
        float w = (st == 0 ? w1 : w2)[si * 65536 + n * 256 + k];
        __nv_bfloat16 hi = __float2bfloat16(w);
        __nv_bfloat16 lo = __float2bfloat16(w - __bfloat162float(hi));
        int ch = k >> 5;
        int wr = (k & 31) >> 1;
        int wp = wr ^ (((n >> 1) & 3) << 2);
        ((__nv_bfloat16*)&g_ewt[st][si][ch][0][n][wp])[k & 1] = hi;
        ((__nv_bfloat16*)&g_ewt[st][si][ch][1][n][wp])[k & 1] = lo;
    }
    if (idx < 2 * 768 * 256) {                  // gru weights: 393216
        int k = idx & 255;
        int e = (idx >> 8) % 768;
        int wh = idx / (768 * 256);
        float w = (wh == 0 ? wih : whh)[e * 256 + k];
        __nv_bfloat16 hi = __float2bfloat16(w);
        __nv_bfloat16 lo = __float2bfloat16(w - __bfloat162float(hi));
        int ny = e >> 8, n = e & 255;
        int ch = k >> 5;
        int wr = (k & 31) >> 1;
        int wp = wr ^ (((n >> 1) & 3) << 2);
        ((__nv_bfloat16*)&g_gwt[wh][ny][ch][0][n][wp])[k & 1] = hi;
        ((__nv_bfloat16*)&g_gwt[wh][ny][ch][1][n][wp])[k & 1] = lo;
    }
}

// inner HMMA: one 32-wide k chunk. Wp points at [hi][256][16] then [lo] at +4096 words.
__device__ __forceinline__ void hmma_chunk(
    const unsigned* Ahw, const unsigned* Alw, const unsigned* Wp,
    float acc[2][8][4], int wm, int wn, int lane, int kc7)
{
#pragma unroll
    for (int ks = 0; ks < 2; ++ks) {
        int wA = kc7 * 16 + ks * 8 + (lane & 3);
        unsigned ah[2][4], al[2][4];
#pragma unroll
        for (int mt = 0; mt < 2; ++mt) {
            int r = wm * 32 + mt * 16 + (lane >> 2);
            const unsigned* ph = Ahw + r * AW_PITCH;
            const unsigned* pl = Alw + r * AW_PITCH;
            ah[mt][0] = ph[wA];                  ah[mt][1] = ph[8 * AW_PITCH + wA];
            ah[mt][2] = ph[wA + 4];              ah[mt][3] = ph[8 * AW_PITCH + wA + 4];
            al[mt][0] = pl[wA];                  al[mt][1] = pl[8 * AW_PITCH + wA];
            al[mt][2] = pl[wA + 4];              al[mt][3] = pl[8 * AW_PITCH + wA + 4];
        }
#pragma unroll
        for (int nf = 0; nf < 8; ++nf) {
            int n = wn * 64 + nf * 8 + (lane >> 2);
            int sw = ((n >> 1) & 3) << 2;
            int w0 = ks * 8 + (lane & 3);
            unsigned bh0 = Wp[n * 16 + (w0 ^ sw)];
            unsigned bh1 = Wp[n * 16 + ((w0 + 4) ^ sw)];
            unsigned bl0 = Wp[4096 + n * 16 + (w0 ^ sw)];
            unsigned bl1 = Wp[4096 + n * 16 + ((w0 + 4) ^ sw)];
#pragma unroll
            for (int mt = 0; mt < 2; ++mt) {
                mma16816(acc[mt][nf], ah[mt][0], ah[mt][1], ah[mt][2], ah[mt][3], bh0, bh1);
                mma16816(acc[mt][nf], al[mt][0], al[mt][1], al[mt][2], al[mt][3], bh0, bh1);
                mma16816(acc[mt][nf], ah[mt][0], ah[mt][1], ah[mt][2], ah[mt][3], bl0, bl1);
            }
        }
    }
}

// ---------------- fused edge MLP (tensor core) ----------------
__global__ void __launch_bounds__(512, 1) edge_tc(
    const int* __restrict__ edges,
    const float* __restrict__ eb1,
    const float* __restrict__ eb2)
{
    extern __shared__ char smem[];
    unsigned sb = smem_u32(smem);
    unsigned* Ahw = (unsigned*)smem;
    unsigned* Alw = Ahw + OFF_ALO_W;
    unsigned* Ww  = Ahw + OFF_W_W;
    int* s_dst = (int*)(smem + OFF_DST_B);
    int* s_src = (int*)(smem + OFF_SRC_B);
    unsigned mbar = sb + OFF_BAR_B;

    int tid = threadIdx.x, lane = tid & 31, wid = tid >> 5;
    int wm = wid >> 2, wn = wid & 3;
    int b = blockIdx.y, si = blockIdx.z;
    int e0 = blockIdx.x * 128;

    if (tid < 128) {
        int2 e2 = ((const int2*)edges)[((size_t)(b * SS + si)) * EE + e0 + tid];
        s_dst[tid] = e2.x;
        s_src[tid] = e2.y;
    }
    if (tid == 0) { MB_INIT(mbar, 1); MB_INIT(mbar + 8, 1); }
    __syncthreads();

    const char* gw = (const char*)&g_ewt[0][si][0][0][0][0];
    if (tid == 0) {
        MB_EXPECT(mbar, 32768);
        bulk_g2s(sb + OFF_W_B, gw, 32768, mbar);
    }

    // gather + hi/lo split into As
    {
        int r = tid >> 2, q = tid & 3;
        const float4* sp = (const float4*)(g_h + ((size_t)b * NN + s_src[r]) * DD) + q * 16;
        unsigned* dh = Ahw + r * AW_PITCH + q * 32;
        unsigned* dl = Alw + r * AW_PITCH + q * 32;
#pragma unroll
        for (int i = 0; i < 16; ++i) {
            float4 v = sp[i];
            float h0 = __bfloat162float(__float2bfloat16(v.x));
            float h1 = __bfloat162float(__float2bfloat16(v.y));
            float h2 = __bfloat162float(__float2bfloat16(v.z));
            float h3 = __bfloat162float(__float2bfloat16(v.w));
            dh[2*i]   = pack2(h0, h1);
            dh[2*i+1] = pack2(h2, h3);
            dl[2*i]   = pack2(v.x - h0, v.y - h1);
            dl[2*i+1] = pack2(v.z - h2, v.w - h3);
        }
    }

    float acc[2][8][4];
#pragma unroll
    for (int mt = 0; mt < 2; ++mt)
#pragma unroll
        for (int nf = 0; nf < 8; ++nf)
#pragma unroll
            for (int i = 0; i < 4; ++i) acc[mt][nf][i] = 0.f;

    int ph[2] = {0, 0};
    const float* b1s = eb1 + si * DD;
    const float* b2s = eb2 + si * DD;

    for (int kc = 0; kc < 16; ++kc) {
        int buf = kc & 1;
        MB_WAIT(mbar + 8 * buf, ph[buf]); ph[buf] ^= 1;
        __syncthreads();
        if (kc < 15 && tid == 0) {
            int nb = buf ^ 1;
            int c1 = kc + 1, st = c1 >> 3, ch = c1 & 7;
            const char* src = (const char*)&g_ewt[st][si][ch][0][0][0];
            MB_EXPECT(mbar + 8 * nb, 32768);
            bulk_g2s(sb + OFF_W_B + nb * 32768, src, 32768, mbar + 8 * nb);
        }
        if (kc == 8) {
            // stage-1 epilogue: bias + leaky -> re-split into As
#pragma unroll
            for (int mt = 0; mt < 2; ++mt) {
#pragma unroll
                for (int nf = 0; nf < 8; ++nf) {
                    int ncol = wn * 64 + nf * 8 + (lane & 3) * 2;
                    float2 bv = *(const float2*)(b1s + ncol);
#pragma unroll
                    for (int half = 0; half < 2; ++half) {
                        int m = wm * 32 + mt * 16 + (lane >> 2) + half * 8;
                        float v0 = acc[mt][nf][half * 2 + 0] + bv.x;
                        float v1 = acc[mt][nf][half * 2 + 1] + bv.y;
                        v0 = v0 > 0.f ? v0 : 0.01f * v0;
                        v1 = v1 > 0.f ? v1 : 0.01f * v1;
                        float h0 = __bfloat162float(__float2bfloat16(v0));
                        float h1 = __bfloat162float(__float2bfloat16(v1));
                        Ahw[m * AW_PITCH + (ncol >> 1)] = pack2(h0, h1);
                        Alw[m * AW_PITCH + (ncol >> 1)] = pack2(v0 - h0, v1 - h1);
                        acc[mt][nf][half * 2 + 0] = 0.f;
                        acc[mt][nf][half * 2 + 1] = 0.f;
                    }
                }
            }
            __syncthreads();
        }
        hmma_chunk(Ahw, Alw, Ww + buf * 8192, acc, wm, wn, lane, kc & 7);
    }

    // stage-2 epilogue: bias + atomic scatter
#pragma unroll
    for (int mt = 0; mt < 2; ++mt) {
#pragma unroll
        for (int half = 0; half < 2; ++half) {
            int m = wm * 32 + mt * 16 + (lane >> 2) + half * 8;
            float* op = g_inc + ((size_t)b * NN + s_dst[m]) * DD;
#pragma unroll
            for (int nf = 0; nf < 8; ++nf) {
                int ncol = wn * 64 + nf * 8 + (lane & 3) * 2;
                float2 bv = *(const float2*)(b2s + ncol);
                atomicAdd(op + ncol,     acc[mt][nf][half * 2 + 0] + bv.x);
                atomicAdd(op + ncol + 1, acc[mt][nf][half * 2 + 1] + bv.y);
            }
        }
    }
}

// ---------------- GRU GEMM (tensor core): C[40000 x 768 slice] = A x W^T + bias ------
__global__ void __launch_bounds__(512, 1) gru_tc(
    const float* __restrict__ A, int which,
    const float* __restrict__ bias, float* __restrict__ C)
{
    extern __shared__ char smem[];
    unsigned sb = smem_u32(smem);
    unsigned* Ahw = (unsigned*)smem;
    unsigned* Alw = Ahw + OFF_ALO_W;
    unsigned* Ww  = Ahw + OFF_W_W;
    unsigned mbar = sb + OFF_BAR_B;

    int tid = threadIdx.x, lane = tid & 31, wid = tid >> 5;
    int wm = wid >> 2, wn = wid & 3;
    int row0 = blockIdx.x * 128;
    int ny = blockIdx.y, col0 = ny * 256;

    if (tid == 0) { MB_INIT(mbar, 1); MB_INIT(mbar + 8, 1); }
    __syncthreads();

    if (tid == 0) {
        MB_EXPECT(mbar, 32768);
        bulk_g2s(sb + OFF_W_B, (const char*)&g_gwt[which][ny][0][0][0][0], 32768, mbar);
    }

    // load + split A rows (clamp OOB rows)
    {
        int r = tid >> 2, q = tid & 3;
        int rg = row0 + r; if (rg >= MROWS) rg = row0;
        const float4* sp = (const float4*)(A + (size_t)rg * DD) + q * 16;
        unsigned* dh = Ahw + r * AW_PITCH + q * 32;
        unsigned* dl = Alw + r * AW_PITCH + q * 32;
#pragma unroll
        for (int i = 0; i < 16; ++i) {
            float4 v = sp[i];
            float h0 = __bfloat162float(__float2bfloat16(v.x));
            float h1 = __bfloat162float(__float2bfloat16(v.y));
            float h2 = __bfloat162float(__float2bfloat16(v.z));
            float h3 = __bfloat162float(__float2bfloat16(v.w));
            dh[2*i]   = pack2(h0, h1);
            dh[2*i+1] = pack2(h2, h3);
            dl[2*i]   = pack2(v.x - h0, v.y - h1);
            dl[2*i+1] = pack2(v.z - h2, v.w - h3);
        }
    }

    float acc[2][8][4];
#pragma unroll
    for (int mt = 0; mt < 2; ++mt)
#pragma unroll
        for (int nf = 0; nf < 8; ++nf)
#pragma unroll
            for (int i = 0; i < 4; ++i) acc[mt][nf][i] = 0.f;

    int ph[2] = {0, 0};
    for (int kc = 0; kc < 8; ++kc) {
        int buf = kc & 1;
        MB_WAIT(mbar + 8 * buf, ph[buf]); ph[buf] ^= 1;
        __syncthreads();
        if (kc < 7 && tid == 0) {
            int nb = buf ^ 1;
            MB_EXPECT(mbar + 8 * nb, 32768);
            bulk_g2s(sb + OFF_W_B + nb * 32768, (const char*)&g_gwt[which][ny][kc + 1][0][0][0],
                     32768, mbar + 8 * nb);
        }
        hmma_chunk(Ahw, Alw, Ww + buf * 8192, acc, wm, wn, lane, kc);
    }

#pragma unroll
    for (int mt = 0; mt < 2; ++mt) {
#pragma unroll
        for (int half = 0; half < 2; ++half) {
            int row = row0 + wm * 32 + mt * 16 + (lane >> 2) + half * 8;
            if (row < MROWS) {
                float* cp = C + (size_t)row * 768 + col0;
#pragma unroll
                for (int nf = 0; nf < 8; ++nf) {
                    int ncol = wn * 64 + nf * 8 + (lane & 3) * 2;
                    float2 bv = *(const float2*)(bias + col0 + ncol);
                    float2 v;
                    v.x = acc[mt][nf][half * 2 + 0] + bv.x;
                    v.y = acc[mt][nf][half * 2 + 1] + bv.y;
                    *(float2*)(cp + ncol) = v;
                }
            }
        }
    }
}

// ---------------- GRU pointwise gates ----------------
__global__ void gru_gate(const float* __restrict__ gi, const float* __restrict__ gh) {
    size_t idx = (size_t)blockIdx.x * 256 + threadIdx.x;
    size_t row = idx >> 8;
    int d = (int)(idx & 255);
    const float* gir = gi + row * 768;
    const float* ghr = gh + row * 768;
    float ir = gir[d], iz = gir[256 + d], in_ = gir[512 + d];
    float hr = ghr[d], hz = ghr[256 + d], hn  = ghr[512 + d];
    float r = 1.f / (1.f + expf(-(ir + hr)));
    float z = 1.f / (1.f + expf(-(iz + hz)));
    float n = tanhf(in_ + r * hn);
    float hv = g_h[idx];
    g_h[idx] = (1.f - z) * n + z * hv;
}

__global__ void node_sum() {
    int b = blockIdx.x, chunk = blockIdx.y;
    int d = threadIdx.x;
    const float* base = g_h + ((size_t)b * NN + chunk * 250) * DD + d;
    float acc = 0.f;
    for (int n = 0; n < 250; ++n) acc += base[(size_t)n * DD];
    atomicAdd(&g_s[b * DD + d], acc);
}

__global__ void head_kernel(const float* __restrict__ ptype,
                            const float* __restrict__ fc1w, const float* __restrict__ fc1b,
                            const float* __restrict__ fc2w, const float* __restrict__ fc2b,
                            const float* __restrict__ fc3w, const float* __restrict__ fc3b,
                            float* __restrict__ out)
{
    int b = blockIdx.x, tid = threadIdx.x;
    __shared__ float xs[257];
    __shared__ float red[256];
    __shared__ float a1[HID], a2[HID];

    float sv = g_s[b * DD + tid];
    float l = logf(sv);
    if (isnan(l)) l = 0.f;
    l = fmaxf(l, 0.f);
    float fm = isinf(l) ? -INFINITY : l;
    red[tid] = fm;
    __syncthreads();
    for (int off = 128; off > 0; off >>= 1) {
        if (tid < off) red[tid] = fmaxf(red[tid], red[tid + off]);
        __syncthreads();
    }
    float fmax = red[0];
    if (isinf(l)) l = fmax;
    xs[tid] = l;
    if (tid == 0) xs[256] = ptype[b];
    __syncthreads();

    if (tid < HID) {
        float acc = fc1b[tid];
        for (int k = 0; k < 257; ++k) acc += fc1w[tid * 257 + k] * xs[k];
        a1[tid] = acc > 0.f ? acc : 0.01f * acc;
    }
    __syncthreads();
    if (tid < HID) {
        float acc = fc2b[tid];
        for (int k = 0; k < HID; ++k) acc += fc2w[tid * HID + k] * a1[k];
        a2[tid] = acc > 0.f ? acc : 0.01f * acc;
    }
    __syncthreads();
    if (tid < OUTD) {
        float acc = fc3b[tid];
        for (int k = 0; k < HID; ++k) acc += fc3w[tid * HID + k] * a2[k];
        out[b * OUTD + tid] = acc;
    }
}

// ---------------- launch ----------------
extern "C" void kernel_launch(void* const* d_in, const int* in_sizes, int n_in,
                              void* d_out, int out_size) {
    const float* nodes = (const float*)d_in[0];
    const int*   edges = (const int*)  d_in[1];
    const float* ptype = (const float*)d_in[2];
    const float* w_ih  = (const float*)d_in[3];
    const float* w_hh  = (const float*)d_in[4];
    const float* b_ih  = (const float*)d_in[5];
    const float* b_hh  = (const float*)d_in[6];
    const float* ew1   = (const float*)d_in[7];
    const float* eb1   = (const float*)d_in[8];
    const float* ew2   = (const float*)d_in[9];
    const float* eb2   = (const float*)d_in[10];
    const float* fc1w  = (const float*)d_in[11];
    const float* fc1b  = (const float*)d_in[12];
    const float* fc2w  = (const float*)d_in[13];
    const float* fc2b  = (const float*)d_in[14];
    const float* fc3w  = (const float*)d_in[15];
    const float* fc3b  = (const float*)d_in[16];
    float* out = (float*)d_out;

    float *p_h, *p_inc, *p_gi, *p_gh, *p_s;
    cudaGetSymbolAddress((void**)&p_h,   g_h);
    cudaGetSymbolAddress((void**)&p_inc, g_inc);
    cudaGetSymbolAddress((void**)&p_gi,  g_gi);
    cudaGetSymbolAddress((void**)&p_gh,  g_gh);
    cudaGetSymbolAddress((void**)&p_s,   g_s);

    cudaFuncSetAttribute(edge_tc, cudaFuncAttributeMaxDynamicSharedMemorySize, TSMEM);
    cudaFuncSetAttribute(gru_tc,  cudaFuncAttributeMaxDynamicSharedMemorySize, TSMEM);

    const int n4_state = BB * NN * DD / 4;
    const int GRID_M = (MROWS + 127) / 128;   // 313

    copy4<<<(n4_state + 255) / 256, 256>>>((float4*)p_h, (const float4*)nodes, n4_state);
    prep_weights<<<1536, 256>>>(ew1, ew2, w_ih, w_hh);

    for (int j = 0; j < NPASS; ++j) {
        zero4<<<(n4_state + 255) / 256, 256>>>((float4*)p_inc, n4_state);
        edge_tc<<<dim3(EE / 128, BB, SS), 512, TSMEM>>>(edges, eb1, eb2);
        gru_tc<<<dim3(GRID_M, 3), 512, TSMEM>>>(p_inc, 0, b_ih, p_gi);
        gru_tc<<<dim3(GRID_M, 3), 512, TSMEM>>>(p_h,   1, b_hh, p_gh);
        gru_gate<<<BB * NN * DD / 256, 256>>>(p_gi, p_gh);
    }

    zero4<<<1, 256>>>((float4*)p_s, BB * DD / 4);
    node_sum<<<dim3(BB, 40), 256>>>();
    head_kernel<<<BB, 256>>>(ptype, fc1w, fc1b, fc2w, fc2b, fc3w, fc3b, out);
}

// round 6
// speedup vs baseline: 3.0271x; 1.0455x over previous
#include <cuda_runtime.h>
#include <cuda_bf16.h>
#include <math.h>

#define BB 4
#define NN 10000
#define DD 256
#define EE 160000
#define SS 2
#define NPASS 6
#define HID 80
#define OUTD 10
#define MROWS (BB * NN)   // 40000
#define AW_PITCH 136      // words per A row (conflict-free for LDS.64 pattern)

// ---------------- device scratch ----------------
__device__ float g_h  [MROWS * DD];
__device__ float g_inc[MROWS * DD];
__device__ float g_gi [MROWS * 3 * DD];
__device__ float g_gh [MROWS * 3 * DD];
__device__ float g_s  [BB * DD];
// pre-split h images: per row 128 words (bf16x2), word order pair-permuted for LDS.64
__device__ __align__(16) unsigned g_hhi[MROWS * 128];
__device__ __align__(16) unsigned g_hlo[MROWS * 128];
// edge weights: [stage][si][chunk8][hi/lo][4096 words]; gru: [which][nslice3][chunk8][hi/lo][4096]
__device__ __align__(16) unsigned g_ewt[2][SS][8][2][4096];
__device__ __align__(16) unsigned g_gwt[2][3][8][2][4096];

// ---------------- PTX helpers ----------------
__device__ __forceinline__ unsigned smem_u32(const void* p) {
    unsigned a;
    asm("{ .reg .u64 t; cvta.to.shared.u64 t, %1; cvt.u32.u64 %0, t; }" : "=r"(a) : "l"(p));
    return a;
}
#define MB_INIT(mb, c) asm volatile("mbarrier.init.shared.b64 [%0], %1;" :: "r"(mb), "r"(c) : "memory")
#define MB_EXPECT(mb, n) asm volatile("mbarrier.arrive.expect_tx.shared.b64 _, [%0], %1;" :: "r"(mb), "r"(n) : "memory")
#define MB_ARRIVE(mb) asm volatile("mbarrier.arrive.shared.b64 _, [%0];" :: "r"(mb) : "memory")
#define MB_WAIT(mb, ph) do { \
    unsigned _m = (mb), _p = (ph), _d; \
    asm volatile("{\n\t.reg .pred p;\n\t" \
        "mbarrier.try_wait.parity.acquire.cta.shared::cta.b64 p, [%1], %2;\n\t" \
        "selp.b32 %0, 1, 0, p;\n\t}" : "=r"(_d) : "r"(_m), "r"(_p) : "memory"); \
    if (!_d) { \
        asm volatile("{\n\t.reg .pred P1;\n\tWL_%=:\n\t" \
            "mbarrier.try_wait.parity.acquire.cta.shared::cta.b64 P1, [%0], %1, 0x989680;\n\t" \
            "@P1 bra.uni WD_%=;\n\tbra.uni WL_%=;\n\tWD_%=:\n\t}" :: "r"(_m), "r"(_p) : "memory"); \
    } \
} while (0)
__device__ __forceinline__ void bulk_g2s(unsigned dst, const void* src, unsigned bytes, unsigned mbar) {
    asm volatile("cp.async.bulk.shared::cluster.global.mbarrier::complete_tx::bytes [%0], [%1], %2, [%3];"
        :: "r"(dst), "l"(src), "r"(bytes), "r"(mbar) : "memory");
}
#define CP16(dst, src) asm volatile("cp.async.cg.shared.global [%0], [%1], 16;" :: "r"(dst), "l"(src) : "memory")
#define CP_COMMIT() asm volatile("cp.async.commit_group;" ::: "memory")
#define CP_WAIT0()  asm volatile("cp.async.wait_group 0;" ::: "memory")
__device__ __forceinline__ void mma16816(float c[4], unsigned a0, unsigned a1, unsigned a2, unsigned a3,
                                         unsigned b0, unsigned b1) {
    asm volatile("mma.sync.aligned.m16n8k16.row.col.f32.bf16.bf16.f32 "
        "{%0,%1,%2,%3}, {%4,%5,%6,%7}, {%8,%9}, {%0,%1,%2,%3};"
        : "+f"(c[0]), "+f"(c[1]), "+f"(c[2]), "+f"(c[3])
        : "r"(a0), "r"(a1), "r"(a2), "r"(a3), "r"(b0), "r"(b1));
}
__device__ __forceinline__ unsigned pack2(float a, float b) {
    __nv_bfloat162 t = __floats2bfloat162_rn(a, b);
    return *(unsigned*)&t;
}
// pair permutation: original k-word w = g*8 + s*4 + q  ->  p = g*8 + q*2 + s
__device__ __forceinline__ int permw(int w) {
    return (w & ~7) | ((w & 3) << 1) | ((w >> 2) & 1);
}

// ---------------- smem layout (bytes) ----------------
#define OFF_ALO_B 69632          /* A_lo at 128*136*4 */
#define OFF_ALO_W 17408
#define OFF_W_B   139264
#define OFF_W_W   34816
#define OFF_DST_B 204800
#define OFF_SRC_B 205312
#define OFF_BAR_B 205824         /* full0, full1, empty0, empty1 */
#define TSMEM     205888

// ---------------- helpers ----------------
__global__ void zero4(float4* __restrict__ dst, int n4) {
    int i = blockIdx.x * 256 + threadIdx.x;
    if (i < n4) dst[i] = make_float4(0.f, 0.f, 0.f, 0.f);
}

// init h (fp32 copy + hi/lo split images)
__global__ void split_init(const float* __restrict__ nodes) {
    size_t i2 = (size_t)blockIdx.x * 256 + threadIdx.x;   // over MROWS*128 pairs
    float2 v = ((const float2*)nodes)[i2];
    ((float2*)g_h)[i2] = v;
    size_t row = i2 >> 7;
    int w = (int)(i2 & 127);
    float h0 = __bfloat162float(__float2bfloat16(v.x));
    float h1 = __bfloat162float(__float2bfloat16(v.y));
    int p = permw(w);
    g_hhi[row * 128 + p] = pack2(h0, h1);
    g_hlo[row * 128 + p] = pack2(v.x - h0, v.y - h1);
}

// bake weights: bf16 hi/lo at pair-permuted + bank-swizzled word positions
__global__ void prep_weights(const float* __restrict__ w1, const float* __restrict__ w2,
                             const float* __restrict__ wih, const float* __restrict__ whh) {
    int idx = blockIdx.x * 256 + threadIdx.x;   // 0 .. 393215
    if (idx < 2 * SS * 256 * 256) {             // edge weights
        int k  = idx & 255;
        int n  = (idx >> 8) & 255;
        int si = (idx >> 16) & 1;
        int st = idx >> 17;
        float w = (st == 0 ? w1 : w2)[si * 65536 + n * 256 + k];
        __nv_bfloat16 hi = __float2bfloat16(w);
        __nv_bfloat16 lo = __float2bfloat16(w - __bfloat162float(hi));
        int ch = k >> 5;
        int wr = (k & 31) >> 1;
        int ks = wr >> 3, s = (wr >> 2) & 1, q = wr & 3;
        int word = n * 16 + ((((ks << 2) + q) ^ (((n >> 1) & 1) << 2)) << 1) + s;
        ((__nv_bfloat16*)&g_ewt[st][si][ch][0][word])[k & 1] = hi;
        ((__nv_bfloat16*)&g_ewt[st][si][ch][1][word])[k & 1] = lo;
    }
    if (idx < 2 * 768 * 256) {                  // gru weights
        int k = idx & 255;
        int e = (idx >> 8) % 768;
        int wh = idx / (768 * 256);
        float w = (wh == 0 ? wih : whh)[e * 256 + k];
        __nv_bfloat16 hi = __float2bfloat16(w);
        __nv_bfloat16 lo = __float2bfloat16(w - __bfloat162float(hi));
        int ny = e >> 8, n = e & 255;
        int ch = k >> 5;
        int wr = (k & 31) >> 1;
        int ks = wr >> 3, s = (wr >> 2) & 1, q = wr & 3;
        int word = n * 16 + ((((ks << 2) + q) ^ (((n >> 1) & 1) << 2)) << 1) + s;
        ((__nv_bfloat16*)&g_gwt[wh][ny][ch][0][word])[k & 1] = hi;
        ((__nv_bfloat16*)&g_gwt[wh][ny][ch][1][word])[k & 1] = lo;
    }
}

// inner HMMA for one 32-k chunk. Wp: [hi 4096 words][lo 4096 words].
__device__ __forceinline__ void hmma_chunk(
    const unsigned* Ahw, const unsigned* Alw, const unsigned* Wp,
    float acc[2][8][4], int wm, int wn, int lane, int kc7)
{
    int q = lane & 3, rr = lane >> 2;
#pragma unroll
    for (int ks = 0; ks < 2; ++ks) {
        int aoff = (kc7 * 2 + ks) * 8 + q * 2;
        uint2 ah[2][2], al[2][2];
#pragma unroll
        for (int mt = 0; mt < 2; ++mt) {
            int r0 = wm * 32 + mt * 16 + rr;
            ah[mt][0] = *(const uint2*)(Ahw + r0 * AW_PITCH + aoff);
            ah[mt][1] = *(const uint2*)(Ahw + (r0 + 8) * AW_PITCH + aoff);
            al[mt][0] = *(const uint2*)(Alw + r0 * AW_PITCH + aoff);
            al[mt][1] = *(const uint2*)(Alw + (r0 + 8) * AW_PITCH + aoff);
        }
#pragma unroll
        for (int nf = 0; nf < 8; ++nf) {
            int n = wn * 64 + nf * 8 + rr;
            int pu = ((((ks << 2) + q) ^ (((n >> 1) & 1) << 2)) << 1);
            uint2 bh = *(const uint2*)(Wp + n * 16 + pu);
            uint2 bl = *(const uint2*)(Wp + 4096 + n * 16 + pu);
#pragma unroll
            for (int mt = 0; mt < 2; ++mt) {
                mma16816(acc[mt][nf], ah[mt][0].x, ah[mt][1].x, ah[mt][0].y, ah[mt][1].y, bh.x, bh.y);
                mma16816(acc[mt][nf], al[mt][0].x, al[mt][1].x, al[mt][0].y, al[mt][1].y, bh.x, bh.y);
                mma16816(acc[mt][nf], ah[mt][0].x, ah[mt][1].x, ah[mt][0].y, ah[mt][1].y, bl.x, bl.y);
            }
        }
    }
}

// ---------------- fused edge MLP ----------------
__global__ void __launch_bounds__(512, 1) edge_tc(
    const int* __restrict__ edges,
    const float* __restrict__ eb1,
    const float* __restrict__ eb2)
{
    extern __shared__ char smem[];
    unsigned sb = smem_u32(smem);
    unsigned* Ahw = (unsigned*)smem;
    unsigned* Alw = Ahw + OFF_ALO_W;
    unsigned* Ww  = Ahw + OFF_W_W;
    int* s_dst = (int*)(smem + OFF_DST_B);
    int* s_src = (int*)(smem + OFF_SRC_B);
    unsigned bar = sb + OFF_BAR_B;

    int tid = threadIdx.x, lane = tid & 31, wid = tid >> 5;
    int wm = wid >> 2, wn = wid & 3;
    int b = blockIdx.y, si = blockIdx.z;
    int e0 = blockIdx.x * 128;

    if (tid < 128) {
        int2 e2 = ((const int2*)edges)[((size_t)(b * SS + si)) * EE + e0 + tid];
        s_dst[tid] = e2.x;
        s_src[tid] = e2.y;
    }
    if (tid == 0) {
        MB_INIT(bar + 0, 1);  MB_INIT(bar + 8, 1);     // full
        MB_INIT(bar + 16, 16); MB_INIT(bar + 24, 16);  // empty (16 warps)
    }
    __syncthreads();

    if (tid == 0) {
#pragma unroll
        for (int g = 0; g < 2; ++g) {
            MB_EXPECT(bar + 8 * g, 32768);
            bulk_g2s(sb + OFF_W_B + g * 32768, &g_ewt[0][si][g][0][0], 32768, bar + 8 * g);
        }
    }

    // gather: straight byte-copy of pre-split rows
    {
        int r = tid >> 2, q = tid & 3;
        size_t grow = ((size_t)b * NN + s_src[r]) * 128;
        const unsigned* ghi = g_hhi + grow + q * 32;
        const unsigned* glo = g_hlo + grow + q * 32;
        unsigned dh = sb + (r * AW_PITCH + q * 32) * 4;
        unsigned dl = dh + OFF_ALO_B;
#pragma unroll
        for (int i = 0; i < 8; ++i) {
            CP16(dh + 16 * i, ghi + 4 * i);
            CP16(dl + 16 * i, glo + 4 * i);
        }
        CP_COMMIT(); CP_WAIT0();
    }
    __syncthreads();

    float acc[2][8][4];
#pragma unroll
    for (int mt = 0; mt < 2; ++mt)
#pragma unroll
        for (int nf = 0; nf < 8; ++nf)
#pragma unroll
            for (int i = 0; i < 4; ++i) acc[mt][nf][i] = 0.f;

    int fph[2] = {0, 0}, eph[2] = {0, 0};
    const float* b1s = eb1 + si * DD;
    const float* b2s = eb2 + si * DD;

    for (int kc = 0; kc < 16; ++kc) {
        int buf = kc & 1;
        MB_WAIT(bar + 8 * buf, fph[buf]); fph[buf] ^= 1;

        if (kc == 8) {
            __syncthreads();   // all warps done with stage-1 A
            // stage-1 epilogue: bias + leaky -> re-split into A (pair-permuted words)
#pragma unroll
            for (int mt = 0; mt < 2; ++mt) {
#pragma unroll
                for (int nf = 0; nf < 8; ++nf) {
                    int ncol = wn * 64 + nf * 8 + (lane & 3) * 2;
                    float2 bv = *(const float2*)(b1s + ncol);
                    int p = permw(ncol >> 1);
#pragma unroll
                    for (int half = 0; half < 2; ++half) {
                        int m = wm * 32 + mt * 16 + (lane >> 2) + half * 8;
                        float v0 = acc[mt][nf][half * 2 + 0] + bv.x;
                        float v1 = acc[mt][nf][half * 2 + 1] + bv.y;
                        v0 = v0 > 0.f ? v0 : 0.01f * v0;
                        v1 = v1 > 0.f ? v1 : 0.01f * v1;
                        float h0 = __bfloat162float(__float2bfloat16(v0));
                        float h1 = __bfloat162float(__float2bfloat16(v1));
                        Ahw[m * AW_PITCH + p] = pack2(h0, h1);
                        Alw[m * AW_PITCH + p] = pack2(v0 - h0, v1 - h1);
                        acc[mt][nf][half * 2 + 0] = 0.f;
                        acc[mt][nf][half * 2 + 1] = 0.f;
                    }
                }
            }
            __syncthreads();   // A2 visible before stage-2 MMAs
        }

        hmma_chunk(Ahw, Alw, Ww + buf * 8192, acc, wm, wn, lane, kc & 7);

        if (lane == 0) MB_ARRIVE(bar + 16 + 8 * buf);
        if (tid == 0 && kc < 14) {
            MB_WAIT(bar + 16 + 8 * buf, eph[buf]); eph[buf] ^= 1;
            int c1 = kc + 2, st = c1 >> 3, ch = c1 & 7;
            MB_EXPECT(bar + 8 * buf, 32768);
            bulk_g2s(sb + OFF_W_B + buf * 32768, &g_ewt[st][si][ch][0][0], 32768, bar + 8 * buf);
        }
    }

    // stage-2 epilogue: bias + vector atomic scatter
#pragma unroll
    for (int mt = 0; mt < 2; ++mt) {
#pragma unroll
        for (int half = 0; half < 2; ++half) {
            int m = wm * 32 + mt * 16 + (lane >> 2) + half * 8;
            float* op = g_inc + ((size_t)b * NN + s_dst[m]) * DD;
#pragma unroll
            for (int nf = 0; nf < 8; ++nf) {
                int ncol = wn * 64 + nf * 8 + (lane & 3) * 2;
                float2 bv = *(const float2*)(b2s + ncol);
                float vx = acc[mt][nf][half * 2 + 0] + bv.x;
                float vy = acc[mt][nf][half * 2 + 1] + bv.y;
                asm volatile("red.global.add.v2.f32 [%0], {%1, %2};"
                    :: "l"(op + ncol), "f"(vx), "f"(vy) : "memory");
            }
        }
    }
}

// ---------------- GRU GEMM: C[rows x 256-col slice] = A x W^T + bias ----------------
__global__ void __launch_bounds__(512, 1) gru_tc(
    const float* __restrict__ A, int which,
    const float* __restrict__ bias, float* __restrict__ C)
{
    extern __shared__ char smem[];
    unsigned sb = smem_u32(smem);
    unsigned* Ahw = (unsigned*)smem;
    unsigned* Alw = Ahw + OFF_ALO_W;
    unsigned* Ww  = Ahw + OFF_W_W;
    unsigned bar = sb + OFF_BAR_B;

    int tid = threadIdx.x, lane = tid & 31, wid = tid >> 5;
    int wm = wid >> 2, wn = wid & 3;
    int row0 = blockIdx.x * 128;
    int ny = blockIdx.y, col0 = ny * 256;

    if (tid == 0) {
        MB_INIT(bar + 0, 1);  MB_INIT(bar + 8, 1);
        MB_INIT(bar + 16, 16); MB_INIT(bar + 24, 16);
    }
    __syncthreads();

    if (tid == 0) {
#pragma unroll
        for (int g = 0; g < 2; ++g) {
            MB_EXPECT(bar + 8 * g, 32768);
            bulk_g2s(sb + OFF_W_B + g * 32768, &g_gwt[which][ny][g][0][0], 32768, bar + 8 * g);
        }
    }

    {
        int r = tid >> 2, q = tid & 3;
        int rg = row0 + r; if (rg >= MROWS) rg = row0;
        if (which == 1) {
            // h: copy pre-split images
            size_t grow = (size_t)rg * 128;
            const unsigned* ghi = g_hhi + grow + q * 32;
            const unsigned* glo = g_hlo + grow + q * 32;
            unsigned dh = sb + (r * AW_PITCH + q * 32) * 4;
            unsigned dl = dh + OFF_ALO_B;
#pragma unroll
            for (int i = 0; i < 8; ++i) {
                CP16(dh + 16 * i, ghi + 4 * i);
                CP16(dl + 16 * i, glo + 4 * i);
            }
            CP_COMMIT(); CP_WAIT0();
        } else {
            // inc: load fp32 + split, pair-permuted writes
            const float4* sp = (const float4*)(A + (size_t)rg * DD) + q * 16;
            unsigned* dh = Ahw + r * AW_PITCH;
            unsigned* dl = Alw + r * AW_PITCH;
#pragma unroll
            for (int i = 0; i < 16; ++i) {
                float4 v = sp[i];
                int w0 = q * 32 + 2 * i;
                float h0 = __bfloat162float(__float2bfloat16(v.x));
                float h1 = __bfloat162float(__float2bfloat16(v.y));
                float h2 = __bfloat162float(__float2bfloat16(v.z));
                float h3 = __bfloat162float(__float2bfloat16(v.w));
                dh[permw(w0)]     = pack2(h0, h1);
                dh[permw(w0 + 1)] = pack2(h2, h3);
                dl[permw(w0)]     = pack2(v.x - h0, v.y - h1);
                dl[permw(w0 + 1)] = pack2(v.z - h2, v.w - h3);
            }
        }
    }
    __syncthreads();

    float acc[2][8][4];
#pragma unroll
    for (int mt = 0; mt < 2; ++mt)
#pragma unroll
        for (int nf = 0; nf < 8; ++nf)
#pragma unroll
            for (int i = 0; i < 4; ++i) acc[mt][nf][i] = 0.f;

    int fph[2] = {0, 0}, eph[2] = {0, 0};
    for (int kc = 0; kc < 8; ++kc) {
        int buf = kc & 1;
        MB_WAIT(bar + 8 * buf, fph[buf]); fph[buf] ^= 1;
        hmma_chunk(Ahw, Alw, Ww + buf * 8192, acc, wm, wn, lane, kc);
        if (lane == 0) MB_ARRIVE(bar + 16 + 8 * buf);
        if (tid == 0 && kc < 6) {
            MB_WAIT(bar + 16 + 8 * buf, eph[buf]); eph[buf] ^= 1;
            MB_EXPECT(bar + 8 * buf, 32768);
            bulk_g2s(sb + OFF_W_B + buf * 32768, &g_gwt[which][ny][kc + 2][0][0], 32768, bar + 8 * buf);
        }
    }

#pragma unroll
    for (int mt = 0; mt < 2; ++mt) {
#pragma unroll
        for (int half = 0; half < 2; ++half) {
            int row = row0 + wm * 32 + mt * 16 + (lane >> 2) + half * 8;
            if (row < MROWS) {
                float* cp = C + (size_t)row * 768 + col0;
#pragma unroll
                for (int nf = 0; nf < 8; ++nf) {
                    int ncol = wn * 64 + nf * 8 + (lane & 3) * 2;
                    float2 bv = *(const float2*)(bias + col0 + ncol);
                    float2 v;
                    v.x = acc[mt][nf][half * 2 + 0] + bv.x;
                    v.y = acc[mt][nf][half * 2 + 1] + bv.y;
                    *(float2*)(cp + ncol) = v;
                }
            }
        }
    }
}

// ---------------- GRU gates (vectorized x2) + h split refresh ----------------
__global__ void gru_gate2(const float* __restrict__ gi, const float* __restrict__ gh) {
    size_t i2 = (size_t)blockIdx.x * 256 + threadIdx.x;   // MROWS*128 pairs
    size_t row = i2 >> 7;
    int w = (int)(i2 & 127);
    int d = w * 2;
    const float* gir = gi + row * 768;
    const float* ghr = gh + row * 768;
    float2 ir = *(const float2*)(gir + d);
    float2 iz = *(const float2*)(gir + 256 + d);
    float2 in2 = *(const float2*)(gir + 512 + d);
    float2 hr = *(const float2*)(ghr + d);
    float2 hz = *(const float2*)(ghr + 256 + d);
    float2 hn = *(const float2*)(ghr + 512 + d);
    float2 hv = ((const float2*)g_h)[i2];
    float r0 = 1.f / (1.f + expf(-(ir.x + hr.x)));
    float r1 = 1.f / (1.f + expf(-(ir.y + hr.y)));
    float z0 = 1.f / (1.f + expf(-(iz.x + hz.x)));
    float z1 = 1.f / (1.f + expf(-(iz.y + hz.y)));
    float n0 = tanhf(in2.x + r0 * hn.x);
    float n1 = tanhf(in2.y + r1 * hn.y);
    float h0 = (1.f - z0) * n0 + z0 * hv.x;
    float h1 = (1.f - z1) * n1 + z1 * hv.y;
    ((float2*)g_h)[i2] = make_float2(h0, h1);
    float e0 = __bfloat162float(__float2bfloat16(h0));
    float e1 = __bfloat162float(__float2bfloat16(h1));
    int p = permw(w);
    g_hhi[row * 128 + p] = pack2(e0, e1);
    g_hlo[row * 128 + p] = pack2(h0 - e0, h1 - e1);
}

// ---------------- node sum + head ----------------
__global__ void node_sum() {
    int b = blockIdx.x, chunk = blockIdx.y;
    int d = threadIdx.x;
    const float* base = g_h + ((size_t)b * NN + chunk * 250) * DD + d;
    float acc = 0.f;
    for (int n = 0; n < 250; ++n) acc += base[(size_t)n * DD];
    atomicAdd(&g_s[b * DD + d], acc);
}

__global__ void head_kernel(const float* __restrict__ ptype,
                            const float* __restrict__ fc1w, const float* __restrict__ fc1b,
                            const float* __restrict__ fc2w, const float* __restrict__ fc2b,
                            const float* __restrict__ fc3w, const float* __restrict__ fc3b,
                            float* __restrict__ out)
{
    int b = blockIdx.x, tid = threadIdx.x;
    __shared__ float xs[257];
    __shared__ float red[256];
    __shared__ float a1[HID], a2[HID];

    float sv = g_s[b * DD + tid];
    float l = logf(sv);
    if (isnan(l)) l = 0.f;
    l = fmaxf(l, 0.f);
    float fm = isinf(l) ? -INFINITY : l;
    red[tid] = fm;
    __syncthreads();
    for (int off = 128; off > 0; off >>= 1) {
        if (tid < off) red[tid] = fmaxf(red[tid], red[tid + off]);
        __syncthreads();
    }
    float fmax = red[0];
    if (isinf(l)) l = fmax;
    xs[tid] = l;
    if (tid == 0) xs[256] = ptype[b];
    __syncthreads();

    if (tid < HID) {
        float acc = fc1b[tid];
        for (int k = 0; k < 257; ++k) acc += fc1w[tid * 257 + k] * xs[k];
        a1[tid] = acc > 0.f ? acc : 0.01f * acc;
    }
    __syncthreads();
    if (tid < HID) {
        float acc = fc2b[tid];
        for (int k = 0; k < HID; ++k) acc += fc2w[tid * HID + k] * a1[k];
        a2[tid] = acc > 0.f ? acc : 0.01f * acc;
    }
    __syncthreads();
    if (tid < OUTD) {
        float acc = fc3b[tid];
        for (int k = 0; k < HID; ++k) acc += fc3w[tid * HID + k] * a2[k];
        out[b * OUTD + tid] = acc;
    }
}

// ---------------- launch ----------------
extern "C" void kernel_launch(void* const* d_in, const int* in_sizes, int n_in,
                              void* d_out, int out_size) {
    const float* nodes = (const float*)d_in[0];
    const int*   edges = (const int*)  d_in[1];
    const float* ptype = (const float*)d_in[2];
    const float* w_ih  = (const float*)d_in[3];
    const float* w_hh  = (const float*)d_in[4];
    const float* b_ih  = (const float*)d_in[5];
    const float* b_hh  = (const float*)d_in[6];
    const float* ew1   = (const float*)d_in[7];
    const float* eb1   = (const float*)d_in[8];
    const float* ew2   = (const float*)d_in[9];
    const float* eb2   = (const float*)d_in[10];
    const float* fc1w  = (const float*)d_in[11];
    const float* fc1b  = (const float*)d_in[12];
    const float* fc2w  = (const float*)d_in[13];
    const float* fc2b  = (const float*)d_in[14];
    const float* fc3w  = (const float*)d_in[15];
    const float* fc3b  = (const float*)d_in[16];
    float* out = (float*)d_out;

    float *p_h, *p_inc, *p_gi, *p_gh, *p_s;
    cudaGetSymbolAddress((void**)&p_h,   g_h);
    cudaGetSymbolAddress((void**)&p_inc, g_inc);
    cudaGetSymbolAddress((void**)&p_gi,  g_gi);
    cudaGetSymbolAddress((void**)&p_gh,  g_gh);
    cudaGetSymbolAddress((void**)&p_s,   g_s);

    cudaFuncSetAttribute(edge_tc, cudaFuncAttributeMaxDynamicSharedMemorySize, TSMEM);
    cudaFuncSetAttribute(gru_tc,  cudaFuncAttributeMaxDynamicSharedMemorySize, TSMEM);

    const int n4_state = MROWS * DD / 4;
    const int GRID_M = (MROWS + 127) / 128;   // 313

    split_init<<<MROWS * 128 / 256, 256>>>(nodes);
    prep_weights<<<1536, 256>>>(ew1, ew2, w_ih, w_hh);

    for (int j = 0; j < NPASS; ++j) {
        zero4<<<(n4_state + 255) / 256, 256>>>((float4*)p_inc, n4_state);
        edge_tc<<<dim3(EE / 128, BB, SS), 512, TSMEM>>>(edges, eb1, eb2);
        gru_tc<<<dim3(GRID_M, 3), 512, TSMEM>>>(p_inc, 0, b_ih, p_gi);
        gru_tc<<<dim3(GRID_M, 3), 512, TSMEM>>>(p_h,   1, b_hh, p_gh);
        gru_gate2<<<MROWS * 128 / 256, 256>>>(p_gi, p_gh);
    }

    zero4<<<1, 256>>>((float4*)p_s, BB * DD / 4);
    node_sum<<<dim3(BB, 40), 256>>>();
    head_kernel<<<BB, 256>>>(ptype, fc1w, fc1b, fc2w, fc2b, fc3w, fc3b, out);
}

// round 7
// speedup vs baseline: 3.5550x; 1.1744x over previous
#include <cuda_runtime.h>
#include <cuda_bf16.h>
#include <math.h>

#define BB 4
#define NN 10000
#define DD 256
#define EE 160000
#define SS 2
#define NPASS 6
#define HID 80
#define OUTD 10
#define MROWS (BB * NN)   // 40000
#define AW_PITCH 132      // words per A row; 4*m mod 32 distinct -> LDSM conflict-free

// ---------------- device scratch ----------------
__device__ float g_h  [MROWS * DD];
__device__ float g_inc[MROWS * DD];
__device__ float g_gi [MROWS * 3 * DD];
__device__ float g_gh [MROWS * 3 * DD];
__device__ float g_s  [BB * DD];
// pre-split h images: per row 128 words (bf16x2), plain k order
__device__ __align__(16) unsigned g_hhi[MROWS * 128];
__device__ __align__(16) unsigned g_hlo[MROWS * 128];
// weights: [.][chunk8][hi/lo][4096 words]; per n-row 16 words with octet-XOR layout
__device__ __align__(16) unsigned g_ewt[2][SS][8][2][4096];
__device__ __align__(16) unsigned g_gwt[2][3][8][2][4096];

// ---------------- PTX helpers ----------------
__device__ __forceinline__ unsigned smem_u32(const void* p) {
    unsigned a;
    asm("{ .reg .u64 t; cvta.to.shared.u64 t, %1; cvt.u32.u64 %0, t; }" : "=r"(a) : "l"(p));
    return a;
}
#define MB_INIT(mb, c) asm volatile("mbarrier.init.shared.b64 [%0], %1;" :: "r"(mb), "r"(c) : "memory")
#define MB_EXPECT(mb, n) asm volatile("mbarrier.arrive.expect_tx.shared.b64 _, [%0], %1;" :: "r"(mb), "r"(n) : "memory")
#define MB_ARRIVE(mb) asm volatile("mbarrier.arrive.shared.b64 _, [%0];" :: "r"(mb) : "memory")
#define MB_WAIT(mb, ph) do { \
    unsigned _m = (mb), _p = (ph), _d; \
    asm volatile("{\n\t.reg .pred p;\n\t" \
        "mbarrier.try_wait.parity.acquire.cta.shared::cta.b64 p, [%1], %2;\n\t" \
        "selp.b32 %0, 1, 0, p;\n\t}" : "=r"(_d) : "r"(_m), "r"(_p) : "memory"); \
    if (!_d) { \
        asm volatile("{\n\t.reg .pred P1;\n\tWL_%=:\n\t" \
            "mbarrier.try_wait.parity.acquire.cta.shared::cta.b64 P1, [%0], %1, 0x989680;\n\t" \
            "@P1 bra.uni WD_%=;\n\tbra.uni WL_%=;\n\tWD_%=:\n\t}" :: "r"(_m), "r"(_p) : "memory"); \
    } \
} while (0)
__device__ __forceinline__ void bulk_g2s(unsigned dst, const void* src, unsigned bytes, unsigned mbar) {
    asm volatile("cp.async.bulk.shared::cluster.global.mbarrier::complete_tx::bytes [%0], [%1], %2, [%3];"
        :: "r"(dst), "l"(src), "r"(bytes), "r"(mbar) : "memory");
}
#define CP16(dst, src) asm volatile("cp.async.cg.shared.global [%0], [%1], 16;" :: "r"(dst), "l"(src) : "memory")
#define CP_COMMIT() asm volatile("cp.async.commit_group;" ::: "memory")
#define CP_WAIT0()  asm volatile("cp.async.wait_group 0;" ::: "memory")
#define LDSM4(r0, r1, r2, r3, a) \
    asm volatile("ldmatrix.sync.aligned.m8n8.x4.shared.b16 {%0,%1,%2,%3}, [%4];" \
        : "=r"(r0), "=r"(r1), "=r"(r2), "=r"(r3) : "r"(a))
__device__ __forceinline__ void mma16816(float c[4], unsigned a0, unsigned a1, unsigned a2, unsigned a3,
                                         unsigned b0, unsigned b1) {
    asm volatile("mma.sync.aligned.m16n8k16.row.col.f32.bf16.bf16.f32 "
        "{%0,%1,%2,%3}, {%4,%5,%6,%7}, {%8,%9}, {%0,%1,%2,%3};"
        : "+f"(c[0]), "+f"(c[1]), "+f"(c[2]), "+f"(c[3])
        : "r"(a0), "r"(a1), "r"(a2), "r"(a3), "r"(b0), "r"(b1));
}
__device__ __forceinline__ unsigned pack2(float a, float b) {
    __nv_bfloat162 t = __floats2bfloat162_rn(a, b);
    return *(unsigned*)&t;
}

// ---------------- smem layout (bytes) ----------------
#define OFF_ALO_B 67584          /* A_lo at 128*132*4 */
#define OFF_W_B   135168         /* 2 x 32KB weight buffers */
#define OFF_DST_B 200704
#define OFF_SRC_B 201216
#define OFF_BAR_B 201728
#define TSMEM     201792

// ---------------- helpers ----------------
__global__ void zero4(float4* __restrict__ dst, int n4) {
    int i = blockIdx.x * 256 + threadIdx.x;
    if (i < n4) dst[i] = make_float4(0.f, 0.f, 0.f, 0.f);
}

__global__ void split_init(const float* __restrict__ nodes) {
    size_t i2 = (size_t)blockIdx.x * 256 + threadIdx.x;   // MROWS*128 pairs
    float2 v = ((const float2*)nodes)[i2];
    ((float2*)g_h)[i2] = v;
    float h0 = __bfloat162float(__float2bfloat16(v.x));
    float h1 = __bfloat162float(__float2bfloat16(v.y));
    g_hhi[i2] = pack2(h0, h1);
    g_hlo[i2] = pack2(v.x - h0, v.y - h1);
}

// bake weights: word = n*16 + ((oct ^ ((n>>1)&3))<<2) + ((k&7)>>1), oct=(k&31)>>3
__global__ void prep_weights(const float* __restrict__ w1, const float* __restrict__ w2,
                             const float* __restrict__ wih, const float* __restrict__ whh) {
    int idx = blockIdx.x * 256 + threadIdx.x;   // 0 .. 393215
    if (idx < 2 * SS * 256 * 256) {
        int k  = idx & 255;
        int n  = (idx >> 8) & 255;
        int si = (idx >> 16) & 1;
        int st = idx >> 17;
        float w = (st == 0 ? w1 : w2)[si * 65536 + n * 256 + k];
        __nv_bfloat16 hi = __float2bfloat16(w);
        __nv_bfloat16 lo = __float2bfloat16(w - __bfloat162float(hi));
        int ch = k >> 5, kk = k & 31;
        int word = n * 16 + (((kk >> 3) ^ ((n >> 1) & 3)) << 2) + ((kk >> 1) & 3);
        ((__nv_bfloat16*)&g_ewt[st][si][ch][0][word])[k & 1] = hi;
        ((__nv_bfloat16*)&g_ewt[st][si][ch][1][word])[k & 1] = lo;
    }
    if (idx < 2 * 768 * 256) {
        int k = idx & 255;
        int e = (idx >> 8) % 768;
        int wh = idx / (768 * 256);
        float w = (wh == 0 ? wih : whh)[e * 256 + k];
        __nv_bfloat16 hi = __float2bfloat16(w);
        __nv_bfloat16 lo = __float2bfloat16(w - __bfloat162float(hi));
        int ny = e >> 8, n = e & 255;
        int ch = k >> 5, kk = k & 31;
        int word = n * 16 + (((kk >> 3) ^ ((n >> 1) & 3)) << 2) + ((kk >> 1) & 3);
        ((__nv_bfloat16*)&g_gwt[wh][ny][ch][0][word])[k & 1] = hi;
        ((__nv_bfloat16*)&g_gwt[wh][ny][ch][1][word])[k & 1] = lo;
    }
}

// one 32-k chunk: aHi/aLo = per-thread A ldsm addr (mt0,ks0); wB = per-thread B addr (hi)
__device__ __forceinline__ void hmma_chunk(
    unsigned aHi, unsigned aLo, unsigned wB, float acc[2][8][4])
{
    unsigned ah[2][2][4], al[2][2][4];
#pragma unroll
    for (int mt = 0; mt < 2; ++mt)
#pragma unroll
        for (int ks = 0; ks < 2; ++ks) {
            unsigned off = mt * (16 * AW_PITCH * 4) + ks * 32;
            LDSM4(ah[mt][ks][0], ah[mt][ks][1], ah[mt][ks][2], ah[mt][ks][3], aHi + off);
            LDSM4(al[mt][ks][0], al[mt][ks][1], al[mt][ks][2], al[mt][ks][3], aLo + off);
        }
#pragma unroll
    for (int ng = 0; ng < 8; ++ng) {
        unsigned bh[4], bl[4];
        LDSM4(bh[0], bh[1], bh[2], bh[3], wB + ng * 512);
        LDSM4(bl[0], bl[1], bl[2], bl[3], wB + ng * 512 + 16384);
#pragma unroll
        for (int ks = 0; ks < 2; ++ks)
#pragma unroll
            for (int mt = 0; mt < 2; ++mt) {
                mma16816(acc[mt][ng], ah[mt][ks][0], ah[mt][ks][1], ah[mt][ks][2], ah[mt][ks][3],
                         bh[2 * ks], bh[2 * ks + 1]);
                mma16816(acc[mt][ng], al[mt][ks][0], al[mt][ks][1], al[mt][ks][2], al[mt][ks][3],
                         bh[2 * ks], bh[2 * ks + 1]);
                mma16816(acc[mt][ng], ah[mt][ks][0], ah[mt][ks][1], ah[mt][ks][2], ah[mt][ks][3],
                         bl[2 * ks], bl[2 * ks + 1]);
            }
    }
}

// ---------------- fused edge MLP ----------------
__global__ void __launch_bounds__(512, 1) edge_tc(
    const int* __restrict__ edges,
    const float* __restrict__ eb1,
    const float* __restrict__ eb2)
{
    extern __shared__ char smem[];
    unsigned sb = smem_u32(smem);
    unsigned* Ahw = (unsigned*)smem;
    unsigned* Alw = Ahw + OFF_ALO_B / 4;
    int* s_dst = (int*)(smem + OFF_DST_B);
    int* s_src = (int*)(smem + OFF_SRC_B);
    unsigned bar = sb + OFF_BAR_B;

    int tid = threadIdx.x, lane = tid & 31, wid = tid >> 5;
    int wm = wid >> 2, wn = wid & 3;
    int b = blockIdx.y, si = blockIdx.z;
    int e0 = blockIdx.x * 128;

    // per-thread LDSM base addresses
    unsigned aHi0 = sb + (wm * 32 + (lane & 15)) * (AW_PITCH * 4) + (lane >> 4) * 16;
    unsigned wOff = ((unsigned)wn * 1024 + (lane & 7) * 16 + (((lane >> 3) ^ ((lane >> 1) & 3)) << 2)) * 4;

    if (tid < 128) {
        int2 e2 = ((const int2*)edges)[((size_t)(b * SS + si)) * EE + e0 + tid];
        s_dst[tid] = e2.x;
        s_src[tid] = e2.y;
    }
    if (tid == 0) {
        MB_INIT(bar + 0, 1);  MB_INIT(bar + 8, 1);     // full
        MB_INIT(bar + 16, 16); MB_INIT(bar + 24, 16);  // empty (16 warps)
    }
    __syncthreads();

    if (tid == 0) {
#pragma unroll
        for (int g = 0; g < 2; ++g) {
            MB_EXPECT(bar + 8 * g, 32768);
            bulk_g2s(sb + OFF_W_B + g * 32768, &g_ewt[0][si][g][0][0], 32768, bar + 8 * g);
        }
    }

    // gather pre-split rows (byte copy)
    {
        int r = tid >> 2, q = tid & 3;
        size_t grow = ((size_t)b * NN + s_src[r]) * 128;
        const unsigned* ghi = g_hhi + grow + q * 32;
        const unsigned* glo = g_hlo + grow + q * 32;
        unsigned dh = sb + (r * AW_PITCH + q * 32) * 4;
        unsigned dl = dh + OFF_ALO_B;
#pragma unroll
        for (int i = 0; i < 8; ++i) {
            CP16(dh + 16 * i, ghi + 4 * i);
            CP16(dl + 16 * i, glo + 4 * i);
        }
        CP_COMMIT(); CP_WAIT0();
    }
    __syncthreads();

    float acc[2][8][4];
#pragma unroll
    for (int mt = 0; mt < 2; ++mt)
#pragma unroll
        for (int ng = 0; ng < 8; ++ng)
#pragma unroll
            for (int i = 0; i < 4; ++i) acc[mt][ng][i] = 0.f;

    int fph[2] = {0, 0}, eph[2] = {0, 0};
    const float* b1s = eb1 + si * DD;
    const float* b2s = eb2 + si * DD;

    for (int kc = 0; kc < 16; ++kc) {
        int buf = kc & 1;
        MB_WAIT(bar + 8 * buf, fph[buf]); fph[buf] ^= 1;

        if (kc == 8) {
            __syncthreads();   // all warps done reading stage-1 A
#pragma unroll
            for (int mt = 0; mt < 2; ++mt) {
#pragma unroll
                for (int nf = 0; nf < 8; ++nf) {
                    int ncol = wn * 64 + nf * 8 + (lane & 3) * 2;
                    float2 bv = *(const float2*)(b1s + ncol);
#pragma unroll
                    for (int half = 0; half < 2; ++half) {
                        int m = wm * 32 + mt * 16 + (lane >> 2) + half * 8;
                        float v0 = acc[mt][nf][half * 2 + 0] + bv.x;
                        float v1 = acc[mt][nf][half * 2 + 1] + bv.y;
                        v0 = v0 > 0.f ? v0 : 0.01f * v0;
                        v1 = v1 > 0.f ? v1 : 0.01f * v1;
                        float h0 = __bfloat162float(__float2bfloat16(v0));
                        float h1 = __bfloat162float(__float2bfloat16(v1));
                        Ahw[m * AW_PITCH + (ncol >> 1)] = pack2(h0, h1);
                        Alw[m * AW_PITCH + (ncol >> 1)] = pack2(v0 - h0, v1 - h1);
                        acc[mt][nf][half * 2 + 0] = 0.f;
                        acc[mt][nf][half * 2 + 1] = 0.f;
                    }
                }
            }
            __syncthreads();   // A2 visible before stage-2 MMAs
        }

        unsigned aHi = aHi0 + (kc & 7) * 64;
        hmma_chunk(aHi, aHi + OFF_ALO_B, sb + OFF_W_B + buf * 32768 + wOff, acc);

        if (lane == 0) MB_ARRIVE(bar + 16 + 8 * buf);
        if (tid == 0 && kc < 14) {
            MB_WAIT(bar + 16 + 8 * buf, eph[buf]); eph[buf] ^= 1;
            int c1 = kc + 2, st = c1 >> 3, ch = c1 & 7;
            MB_EXPECT(bar + 8 * buf, 32768);
            bulk_g2s(sb + OFF_W_B + buf * 32768, &g_ewt[st][si][ch][0][0], 32768, bar + 8 * buf);
        }
    }

    // stage-2 epilogue: bias + vector atomic scatter
#pragma unroll
    for (int mt = 0; mt < 2; ++mt) {
#pragma unroll
        for (int half = 0; half < 2; ++half) {
            int m = wm * 32 + mt * 16 + (lane >> 2) + half * 8;
            float* op = g_inc + ((size_t)b * NN + s_dst[m]) * DD;
#pragma unroll
            for (int nf = 0; nf < 8; ++nf) {
                int ncol = wn * 64 + nf * 8 + (lane & 3) * 2;
                float2 bv = *(const float2*)(b2s + ncol);
                float vx = acc[mt][nf][half * 2 + 0] + bv.x;
                float vy = acc[mt][nf][half * 2 + 1] + bv.y;
                asm volatile("red.global.add.v2.f32 [%0], {%1, %2};"
                    :: "l"(op + ncol), "f"(vx), "f"(vy) : "memory");
            }
        }
    }
}

// ---------------- GRU GEMM ----------------
__global__ void __launch_bounds__(512, 1) gru_tc(
    const float* __restrict__ A, int which,
    const float* __restrict__ bias, float* __restrict__ C)
{
    extern __shared__ char smem[];
    unsigned sb = smem_u32(smem);
    unsigned* Ahw = (unsigned*)smem;
    unsigned* Alw = Ahw + OFF_ALO_B / 4;
    unsigned bar = sb + OFF_BAR_B;

    int tid = threadIdx.x, lane = tid & 31, wid = tid >> 5;
    int wm = wid >> 2, wn = wid & 3;
    int row0 = blockIdx.x * 128;
    int ny = blockIdx.y, col0 = ny * 256;

    unsigned aHi0 = sb + (wm * 32 + (lane & 15)) * (AW_PITCH * 4) + (lane >> 4) * 16;
    unsigned wOff = ((unsigned)wn * 1024 + (lane & 7) * 16 + (((lane >> 3) ^ ((lane >> 1) & 3)) << 2)) * 4;

    if (tid == 0) {
        MB_INIT(bar + 0, 1);  MB_INIT(bar + 8, 1);
        MB_INIT(bar + 16, 16); MB_INIT(bar + 24, 16);
    }
    __syncthreads();

    if (tid == 0) {
#pragma unroll
        for (int g = 0; g < 2; ++g) {
            MB_EXPECT(bar + 8 * g, 32768);
            bulk_g2s(sb + OFF_W_B + g * 32768, &g_gwt[which][ny][g][0][0], 32768, bar + 8 * g);
        }
    }

    {
        int r = tid >> 2, q = tid & 3;
        int rg = row0 + r; if (rg >= MROWS) rg = row0;
        if (which == 1) {
            size_t grow = (size_t)rg * 128;
            const unsigned* ghi = g_hhi + grow + q * 32;
            const unsigned* glo = g_hlo + grow + q * 32;
            unsigned dh = sb + (r * AW_PITCH + q * 32) * 4;
            unsigned dl = dh + OFF_ALO_B;
#pragma unroll
            for (int i = 0; i < 8; ++i) {
                CP16(dh + 16 * i, ghi + 4 * i);
                CP16(dl + 16 * i, glo + 4 * i);
            }
            CP_COMMIT(); CP_WAIT0();
        } else {
            const float4* sp = (const float4*)(A + (size_t)rg * DD) + q * 16;
            unsigned* dh = Ahw + r * AW_PITCH + q * 32;
            unsigned* dl = Alw + r * AW_PITCH + q * 32;
#pragma unroll
            for (int i = 0; i < 16; ++i) {
                float4 v = sp[i];
                float h0 = __bfloat162float(__float2bfloat16(v.x));
                float h1 = __bfloat162float(__float2bfloat16(v.y));
                float h2 = __bfloat162float(__float2bfloat16(v.z));
                float h3 = __bfloat162float(__float2bfloat16(v.w));
                dh[2 * i]     = pack2(h0, h1);
                dh[2 * i + 1] = pack2(h2, h3);
                dl[2 * i]     = pack2(v.x - h0, v.y - h1);
                dl[2 * i + 1] = pack2(v.z - h2, v.w - h3);
            }
        }
    }
    __syncthreads();

    float acc[2][8][4];
#pragma unroll
    for (int mt = 0; mt < 2; ++mt)
#pragma unroll
        for (int ng = 0; ng < 8; ++ng)
#pragma unroll
            for (int i = 0; i < 4; ++i) acc[mt][ng][i] = 0.f;

    int fph[2] = {0, 0}, eph[2] = {0, 0};
    for (int kc = 0; kc < 8; ++kc) {
        int buf = kc & 1;
        MB_WAIT(bar + 8 * buf, fph[buf]); fph[buf] ^= 1;
        unsigned aHi = aHi0 + kc * 64;
        hmma_chunk(aHi, aHi + OFF_ALO_B, sb + OFF_W_B + buf * 32768 + wOff, acc);
        if (lane == 0) MB_ARRIVE(bar + 16 + 8 * buf);
        if (tid == 0 && kc < 6) {
            MB_WAIT(bar + 16 + 8 * buf, eph[buf]); eph[buf] ^= 1;
            MB_EXPECT(bar + 8 * buf, 32768);
            bulk_g2s(sb + OFF_W_B + buf * 32768, &g_gwt[which][ny][kc + 2][0][0], 32768, bar + 8 * buf);
        }
    }

#pragma unroll
    for (int mt = 0; mt < 2; ++mt) {
#pragma unroll
        for (int half = 0; half < 2; ++half) {
            int row = row0 + wm * 32 + mt * 16 + (lane >> 2) + half * 8;
            if (row < MROWS) {
                float* cp = C + (size_t)row * 768 + col0;
#pragma unroll
                for (int nf = 0; nf < 8; ++nf) {
                    int ncol = wn * 64 + nf * 8 + (lane & 3) * 2;
                    float2 bv = *(const float2*)(bias + col0 + ncol);
                    float2 v;
                    v.x = acc[mt][nf][half * 2 + 0] + bv.x;
                    v.y = acc[mt][nf][half * 2 + 1] + bv.y;
                    *(float2*)(cp + ncol) = v;
                }
            }
        }
    }
}

// ---------------- GRU gates + h split refresh ----------------
__global__ void gru_gate2(const float* __restrict__ gi, const float* __restrict__ gh) {
    size_t i2 = (size_t)blockIdx.x * 256 + threadIdx.x;
    size_t row = i2 >> 7;
    int d = (int)(i2 & 127) * 2;
    const float* gir = gi + row * 768;
    const float* ghr = gh + row * 768;
    float2 ir = *(const float2*)(gir + d);
    float2 iz = *(const float2*)(gir + 256 + d);
    float2 in2 = *(const float2*)(gir + 512 + d);
    float2 hr = *(const float2*)(ghr + d);
    float2 hz = *(const float2*)(ghr + 256 + d);
    float2 hn = *(const float2*)(ghr + 512 + d);
    float2 hv = ((const float2*)g_h)[i2];
    float r0 = 1.f / (1.f + expf(-(ir.x + hr.x)));
    float r1 = 1.f / (1.f + expf(-(ir.y + hr.y)));
    float z0 = 1.f / (1.f + expf(-(iz.x + hz.x)));
    float z1 = 1.f / (1.f + expf(-(iz.y + hz.y)));
    float n0 = tanhf(in2.x + r0 * hn.x);
    float n1 = tanhf(in2.y + r1 * hn.y);
    float h0 = (1.f - z0) * n0 + z0 * hv.x;
    float h1 = (1.f - z1) * n1 + z1 * hv.y;
    ((float2*)g_h)[i2] = make_float2(h0, h1);
    float e0 = __bfloat162float(__float2bfloat16(h0));
    float e1 = __bfloat162float(__float2bfloat16(h1));
    g_hhi[i2] = pack2(e0, e1);
    g_hlo[i2] = pack2(h0 - e0, h1 - e1);
}

// ---------------- node sum + head ----------------
__global__ void node_sum() {
    int b = blockIdx.x, chunk = blockIdx.y;
    int d = threadIdx.x;
    const float* base = g_h + ((size_t)b * NN + chunk * 250) * DD + d;
    float acc = 0.f;
    for (int n = 0; n < 250; ++n) acc += base[(size_t)n * DD];
    atomicAdd(&g_s[b * DD + d], acc);
}

__global__ void head_kernel(const float* __restrict__ ptype,
                            const float* __restrict__ fc1w, const float* __restrict__ fc1b,
                            const float* __restrict__ fc2w, const float* __restrict__ fc2b,
                            const float* __restrict__ fc3w, const float* __restrict__ fc3b,
                            float* __restrict__ out)
{
    int b = blockIdx.x, tid = threadIdx.x;
    __shared__ float xs[257];
    __shared__ float red[256];
    __shared__ float a1[HID], a2[HID];

    float sv = g_s[b * DD + tid];
    float l = logf(sv);
    if (isnan(l)) l = 0.f;
    l = fmaxf(l, 0.f);
    float fm = isinf(l) ? -INFINITY : l;
    red[tid] = fm;
    __syncthreads();
    for (int off = 128; off > 0; off >>= 1) {
        if (tid < off) red[tid] = fmaxf(red[tid], red[tid + off]);
        __syncthreads();
    }
    float fmax = red[0];
    if (isinf(l)) l = fmax;
    xs[tid] = l;
    if (tid == 0) xs[256] = ptype[b];
    __syncthreads();

    if (tid < HID) {
        float acc = fc1b[tid];
        for (int k = 0; k < 257; ++k) acc += fc1w[tid * 257 + k] * xs[k];
        a1[tid] = acc > 0.f ? acc : 0.01f * acc;
    }
    __syncthreads();
    if (tid < HID) {
        float acc = fc2b[tid];
        for (int k = 0; k < HID; ++k) acc += fc2w[tid * HID + k] * a1[k];
        a2[tid] = acc > 0.f ? acc : 0.01f * acc;
    }
    __syncthreads();
    if (tid < OUTD) {
        float acc = fc3b[tid];
        for (int k = 0; k < HID; ++k) acc += fc3w[tid * HID + k] * a2[k];
        out[b * OUTD + tid] = acc;
    }
}

// ---------------- launch ----------------
extern "C" void kernel_launch(void* const* d_in, const int* in_sizes, int n_in,
                              void* d_out, int out_size) {
    const float* nodes = (const float*)d_in[0];
    const int*   edges = (const int*)  d_in[1];
    const float* ptype = (const float*)d_in[2];
    const float* w_ih  = (const float*)d_in[3];
    const float* w_hh  = (const float*)d_in[4];
    const float* b_ih  = (const float*)d_in[5];
    const float* b_hh  = (const float*)d_in[6];
    const float* ew1   = (const float*)d_in[7];
    const float* eb1   = (const float*)d_in[8];
    const float* ew2   = (const float*)d_in[9];
    const float* eb2   = (const float*)d_in[10];
    const float* fc1w  = (const float*)d_in[11];
    const float* fc1b  = (const float*)d_in[12];
    const float* fc2w  = (const float*)d_in[13];
    const float* fc2b  = (const float*)d_in[14];
    const float* fc3w  = (const float*)d_in[15];
    const float* fc3b  = (const float*)d_in[16];
    float* out = (float*)d_out;

    float *p_h, *p_inc, *p_gi, *p_gh, *p_s;
    cudaGetSymbolAddress((void**)&p_h,   g_h);
    cudaGetSymbolAddress((void**)&p_inc, g_inc);
    cudaGetSymbolAddress((void**)&p_gi,  g_gi);
    cudaGetSymbolAddress((void**)&p_gh,  g_gh);
    cudaGetSymbolAddress((void**)&p_s,   g_s);

    cudaFuncSetAttribute(edge_tc, cudaFuncAttributeMaxDynamicSharedMemorySize, TSMEM);
    cudaFuncSetAttribute(gru_tc,  cudaFuncAttributeMaxDynamicSharedMemorySize, TSMEM);

    const int n4_state = MROWS * DD / 4;
    const int GRID_M = (MROWS + 127) / 128;   // 313

    split_init<<<MROWS * 128 / 256, 256>>>(nodes);
    prep_weights<<<1536, 256>>>(ew1, ew2, w_ih, w_hh);

    for (int j = 0; j < NPASS; ++j) {
        zero4<<<(n4_state + 255) / 256, 256>>>((float4*)p_inc, n4_state);
        edge_tc<<<dim3(EE / 128, BB, SS), 512, TSMEM>>>(edges, eb1, eb2);
        gru_tc<<<dim3(GRID_M, 3), 512, TSMEM>>>(p_inc, 0, b_ih, p_gi);
        gru_tc<<<dim3(GRID_M, 3), 512, TSMEM>>>(p_h,   1, b_hh, p_gh);
        gru_gate2<<<MROWS * 128 / 256, 256>>>(p_gi, p_gh);
    }

    zero4<<<1, 256>>>((float4*)p_s, BB * DD / 4);
    node_sum<<<dim3(BB, 40), 256>>>();
    head_kernel<<<BB, 256>>>(ptype, fc1w, fc1b, fc2w, fc2b, fc3w, fc3b, out);
}

// round 8
// speedup vs baseline: 3.9196x; 1.1026x over previous
#include <cuda_runtime.h>
#include <cuda_bf16.h>
#include <math.h>

#define BB 4
#define NN 10000
#define DD 256
#define EE 160000
#define SS 2
#define NPASS 6
#define HID 80
#define OUTD 10
#define MROWS (BB * NN)   // 40000
#define AW_PITCH 132      // words per A row (528B): LDSM conflict-free

// ---------------- device scratch ----------------
__device__ float g_h  [MROWS * DD];
__device__ float g_inc[MROWS * DD];
__device__ float g_gi [MROWS * 3 * DD];
__device__ float g_gh [MROWS * 3 * DD];
__device__ float g_s  [BB * DD];
// pre-split h images: per row 128 words (bf16x2), plain k order
__device__ __align__(16) unsigned g_hhi[MROWS * 128];
__device__ __align__(16) unsigned g_hlo[MROWS * 128];
// weights in 16-k chunks: [.][chunk16][hi/lo][2048 words]; per n-row 8 words, oct-XOR layout
__device__ __align__(16) unsigned g_ewt[2][SS][16][2][2048];
__device__ __align__(16) unsigned g_gwt[2][3][16][2][2048];

// ---------------- PTX helpers ----------------
__device__ __forceinline__ unsigned smem_u32(const void* p) {
    unsigned a;
    asm("{ .reg .u64 t; cvta.to.shared.u64 t, %1; cvt.u32.u64 %0, t; }" : "=r"(a) : "l"(p));
    return a;
}
#define MB_INIT(mb, c) asm volatile("mbarrier.init.shared.b64 [%0], %1;" :: "r"(mb), "r"(c) : "memory")
#define MB_EXPECT(mb, n) asm volatile("mbarrier.arrive.expect_tx.shared.b64 _, [%0], %1;" :: "r"(mb), "r"(n) : "memory")
#define MB_ARRIVE(mb) asm volatile("mbarrier.arrive.shared.b64 _, [%0];" :: "r"(mb) : "memory")
#define MB_WAIT(mb, ph) do { \
    unsigned _m = (mb), _p = (ph), _d; \
    asm volatile("{\n\t.reg .pred p;\n\t" \
        "mbarrier.try_wait.parity.acquire.cta.shared::cta.b64 p, [%1], %2;\n\t" \
        "selp.b32 %0, 1, 0, p;\n\t}" : "=r"(_d) : "r"(_m), "r"(_p) : "memory"); \
    if (!_d) { \
        asm volatile("{\n\t.reg .pred P1;\n\tWL_%=:\n\t" \
            "mbarrier.try_wait.parity.acquire.cta.shared::cta.b64 P1, [%0], %1, 0x989680;\n\t" \
            "@P1 bra.uni WD_%=;\n\tbra.uni WL_%=;\n\tWD_%=:\n\t}" :: "r"(_m), "r"(_p) : "memory"); \
    } \
} while (0)
__device__ __forceinline__ void bulk_g2s(unsigned dst, const void* src, unsigned bytes, unsigned mbar) {
    asm volatile("cp.async.bulk.shared::cluster.global.mbarrier::complete_tx::bytes [%0], [%1], %2, [%3];"
        :: "r"(dst), "l"(src), "r"(bytes), "r"(mbar) : "memory");
}
#define CP16(dst, src) asm volatile("cp.async.cg.shared.global [%0], [%1], 16;" :: "r"(dst), "l"(src) : "memory")
#define CP_COMMIT() asm volatile("cp.async.commit_group;" ::: "memory")
#define CP_WAIT0()  asm volatile("cp.async.wait_group 0;" ::: "memory")
#define LDSM4(r0, r1, r2, r3, a) \
    asm volatile("ldmatrix.sync.aligned.m8n8.x4.shared.b16 {%0,%1,%2,%3}, [%4];" \
        : "=r"(r0), "=r"(r1), "=r"(r2), "=r"(r3) : "r"(a))
__device__ __forceinline__ void mma16816(float c[4], unsigned a0, unsigned a1, unsigned a2, unsigned a3,
                                         unsigned b0, unsigned b1) {
    asm volatile("mma.sync.aligned.m16n8k16.row.col.f32.bf16.bf16.f32 "
        "{%0,%1,%2,%3}, {%4,%5,%6,%7}, {%8,%9}, {%0,%1,%2,%3};"
        : "+f"(c[0]), "+f"(c[1]), "+f"(c[2]), "+f"(c[3])
        : "r"(a0), "r"(a1), "r"(a2), "r"(a3), "r"(b0), "r"(b1));
}
__device__ __forceinline__ unsigned pack2(float a, float b) {
    __nv_bfloat162 t = __floats2bfloat162_rn(a, b);
    return *(unsigned*)&t;
}

// ---------------- smem layout (bytes): A_hi | A_lo | Wx2 | dst | src | bars ----------------
#define OFF_ALO_B 33792          /* 64*132*4 */
#define OFF_W_B   67584          /* 2 x 16KB weight buffers */
#define OFF_DST_B 100352
#define OFF_SRC_B 100608
#define OFF_BAR_B 100864
#define TSMEM     100928

// ---------------- helpers ----------------
__global__ void zero4(float4* __restrict__ dst, int n4) {
    int i = blockIdx.x * 256 + threadIdx.x;
    if (i < n4) dst[i] = make_float4(0.f, 0.f, 0.f, 0.f);
}

__global__ void split_init(const float* __restrict__ nodes) {
    size_t i2 = (size_t)blockIdx.x * 256 + threadIdx.x;   // MROWS*128 pairs
    float2 v = ((const float2*)nodes)[i2];
    ((float2*)g_h)[i2] = v;
    float h0 = __bfloat162float(__float2bfloat16(v.x));
    float h1 = __bfloat162float(__float2bfloat16(v.y));
    g_hhi[i2] = pack2(h0, h1);
    g_hlo[i2] = pack2(v.x - h0, v.y - h1);
}

// bake: 16-k chunks; word = n*8 + ((oct ^ ((n>>2)&1))<<2) + ((k&7)>>1), oct=(k>>3)&1
__global__ void prep_weights(const float* __restrict__ w1, const float* __restrict__ w2,
                             const float* __restrict__ wih, const float* __restrict__ whh) {
    int idx = blockIdx.x * 256 + threadIdx.x;   // 0 .. 393215
    if (idx < 2 * SS * 256 * 256) {
        int k  = idx & 255;
        int n  = (idx >> 8) & 255;
        int si = (idx >> 16) & 1;
        int st = idx >> 17;
        float w = (st == 0 ? w1 : w2)[si * 65536 + n * 256 + k];
        __nv_bfloat16 hi = __float2bfloat16(w);
        __nv_bfloat16 lo = __float2bfloat16(w - __bfloat162float(hi));
        int ch = k >> 4;
        int word = n * 8 + (((((k >> 3) & 1)) ^ ((n >> 2) & 1)) << 2) + ((k & 7) >> 1);
        ((__nv_bfloat16*)&g_ewt[st][si][ch][0][word])[k & 1] = hi;
        ((__nv_bfloat16*)&g_ewt[st][si][ch][1][word])[k & 1] = lo;
    }
    if (idx < 2 * 768 * 256) {
        int k = idx & 255;
        int e = (idx >> 8) % 768;
        int wh = idx / (768 * 256);
        float w = (wh == 0 ? wih : whh)[e * 256 + k];
        __nv_bfloat16 hi = __float2bfloat16(w);
        __nv_bfloat16 lo = __float2bfloat16(w - __bfloat162float(hi));
        int ny = e >> 8, n = e & 255;
        int ch = k >> 4;
        int word = n * 8 + (((((k >> 3) & 1)) ^ ((n >> 2) & 1)) << 2) + ((k & 7) >> 1);
        ((__nv_bfloat16*)&g_gwt[wh][ny][ch][0][word])[k & 1] = hi;
        ((__nv_bfloat16*)&g_gwt[wh][ny][ch][1][word])[k & 1] = lo;
    }
}

// one 16-k chunk. aHi/aLo: per-thread A LDSM addr (mt0). wB: per-thread B addr (hi buf).
__device__ __forceinline__ void hmma_chunk16(
    unsigned aHi, unsigned aLo, unsigned wB, float acc[2][8][4])
{
    unsigned ah[2][4], al[2][4];
#pragma unroll
    for (int mt = 0; mt < 2; ++mt) {
        unsigned off = mt * (16 * AW_PITCH * 4);
        LDSM4(ah[mt][0], ah[mt][1], ah[mt][2], ah[mt][3], aHi + off);
        LDSM4(al[mt][0], al[mt][1], al[mt][2], al[mt][3], aLo + off);
    }
#pragma unroll
    for (int p = 0; p < 4; ++p) {
        unsigned bh[4], bl[4];
        LDSM4(bh[0], bh[1], bh[2], bh[3], wB + p * 512);
        LDSM4(bl[0], bl[1], bl[2], bl[3], wB + p * 512 + 8192);
#pragma unroll
        for (int mt = 0; mt < 2; ++mt) {
            mma16816(acc[mt][2*p],   ah[mt][0], ah[mt][1], ah[mt][2], ah[mt][3], bh[0], bh[1]);
            mma16816(acc[mt][2*p],   al[mt][0], al[mt][1], al[mt][2], al[mt][3], bh[0], bh[1]);
            mma16816(acc[mt][2*p],   ah[mt][0], ah[mt][1], ah[mt][2], ah[mt][3], bl[0], bl[1]);
            mma16816(acc[mt][2*p+1], ah[mt][0], ah[mt][1], ah[mt][2], ah[mt][3], bh[2], bh[3]);
            mma16816(acc[mt][2*p+1], al[mt][0], al[mt][1], al[mt][2], al[mt][3], bh[2], bh[3]);
            mma16816(acc[mt][2*p+1], ah[mt][0], ah[mt][1], ah[mt][2], ah[mt][3], bl[2], bl[3]);
        }
    }
}

// per-thread B address offset (bytes, within a 16KB buffer)
__device__ __forceinline__ unsigned b_thread_off(int wn, int lane) {
    return ((unsigned)(wn * 512 + ((lane >> 4) & 1) * 64 + (lane & 7) * 8) << 2)
         + ((((lane >> 3) ^ (lane >> 2)) & 1) << 4);
}

// ---------------- fused edge MLP: 64 edges/CTA, 256 threads, 2 CTA/SM ----------------
__global__ void __launch_bounds__(256, 2) edge_tc(
    const int* __restrict__ edges,
    const float* __restrict__ eb1,
    const float* __restrict__ eb2)
{
    extern __shared__ char smem[];
    unsigned sb = smem_u32(smem);
    unsigned* Ahw = (unsigned*)smem;
    unsigned* Alw = Ahw + OFF_ALO_B / 4;
    int* s_dst = (int*)(smem + OFF_DST_B);
    int* s_src = (int*)(smem + OFF_SRC_B);
    unsigned bar = sb + OFF_BAR_B;

    int tid = threadIdx.x, lane = tid & 31, wid = tid >> 5;
    int wm = wid >> 2, wn = wid & 3;
    int b = blockIdx.y, si = blockIdx.z;
    int e0 = blockIdx.x * 64;

    unsigned aHi0 = sb + (wm * 32 + (lane & 15)) * (AW_PITCH * 4) + (lane >> 4) * 16;
    unsigned wOff = b_thread_off(wn, lane);

    if (tid < 64) {
        int2 e2 = ((const int2*)edges)[((size_t)(b * SS + si)) * EE + e0 + tid];
        s_dst[tid] = e2.x;
        s_src[tid] = e2.y;
    }
    if (tid == 0) {
        MB_INIT(bar + 0, 1);  MB_INIT(bar + 8, 1);   // full
        MB_INIT(bar + 16, 8); MB_INIT(bar + 24, 8);  // empty (8 warps)
    }
    __syncthreads();

    if (tid == 0) {
#pragma unroll
        for (int g = 0; g < 2; ++g) {
            MB_EXPECT(bar + 8 * g, 16384);
            bulk_g2s(sb + OFF_W_B + g * 16384, &g_ewt[0][si][g][0][0], 16384, bar + 8 * g);
        }
    }

    // gather pre-split rows (byte copy)
    {
        int r = tid >> 2, q = tid & 3;
        size_t grow = ((size_t)b * NN + s_src[r]) * 128;
        const unsigned* ghi = g_hhi + grow + q * 32;
        const unsigned* glo = g_hlo + grow + q * 32;
        unsigned dh = sb + (r * AW_PITCH + q * 32) * 4;
        unsigned dl = dh + OFF_ALO_B;
#pragma unroll
        for (int i = 0; i < 8; ++i) {
            CP16(dh + 16 * i, ghi + 4 * i);
            CP16(dl + 16 * i, glo + 4 * i);
        }
        CP_COMMIT(); CP_WAIT0();
    }
    __syncthreads();

    float acc[2][8][4];
#pragma unroll
    for (int mt = 0; mt < 2; ++mt)
#pragma unroll
        for (int ng = 0; ng < 8; ++ng)
#pragma unroll
            for (int i = 0; i < 4; ++i) acc[mt][ng][i] = 0.f;

    int fph[2] = {0, 0}, eph[2] = {0, 0};
    const float* b1s = eb1 + si * DD;
    const float* b2s = eb2 + si * DD;

    for (int kc = 0; kc < 32; ++kc) {
        int buf = kc & 1;
        MB_WAIT(bar + 8 * buf, fph[buf]); fph[buf] ^= 1;

        if (kc == 16) {
            __syncthreads();   // all warps done reading stage-1 A
#pragma unroll
            for (int mt = 0; mt < 2; ++mt) {
#pragma unroll
                for (int nf = 0; nf < 8; ++nf) {
                    int ncol = wn * 64 + nf * 8 + (lane & 3) * 2;
                    float2 bv = *(const float2*)(b1s + ncol);
#pragma unroll
                    for (int half = 0; half < 2; ++half) {
                        int m = wm * 32 + mt * 16 + (lane >> 2) + half * 8;
                        float v0 = acc[mt][nf][half * 2 + 0] + bv.x;
                        float v1 = acc[mt][nf][half * 2 + 1] + bv.y;
                        v0 = v0 > 0.f ? v0 : 0.01f * v0;
                        v1 = v1 > 0.f ? v1 : 0.01f * v1;
                        float h0 = __bfloat162float(__float2bfloat16(v0));
                        float h1 = __bfloat162float(__float2bfloat16(v1));
                        Ahw[m * AW_PITCH + (ncol >> 1)] = pack2(h0, h1);
                        Alw[m * AW_PITCH + (ncol >> 1)] = pack2(v0 - h0, v1 - h1);
                        acc[mt][nf][half * 2 + 0] = 0.f;
                        acc[mt][nf][half * 2 + 1] = 0.f;
                    }
                }
            }
            __syncthreads();   // A2 visible before stage-2 MMAs
        }

        hmma_chunk16(aHi0 + (kc & 15) * 32, aHi0 + (kc & 15) * 32 + OFF_ALO_B,
                     sb + OFF_W_B + buf * 16384 + wOff, acc);

        if (lane == 0) MB_ARRIVE(bar + 16 + 8 * buf);
        if (tid == 0 && kc < 30) {
            MB_WAIT(bar + 16 + 8 * buf, eph[buf]); eph[buf] ^= 1;
            int c1 = kc + 2, st = c1 >> 4, ch = c1 & 15;
            MB_EXPECT(bar + 8 * buf, 16384);
            bulk_g2s(sb + OFF_W_B + buf * 16384, &g_ewt[st][si][ch][0][0], 16384, bar + 8 * buf);
        }
    }

    // stage-2 epilogue: bias + vector atomic scatter
#pragma unroll
    for (int mt = 0; mt < 2; ++mt) {
#pragma unroll
        for (int half = 0; half < 2; ++half) {
            int m = wm * 32 + mt * 16 + (lane >> 2) + half * 8;
            float* op = g_inc + ((size_t)b * NN + s_dst[m]) * DD;
#pragma unroll
            for (int nf = 0; nf < 8; ++nf) {
                int ncol = wn * 64 + nf * 8 + (lane & 3) * 2;
                float2 bv = *(const float2*)(b2s + ncol);
                float vx = acc[mt][nf][half * 2 + 0] + bv.x;
                float vy = acc[mt][nf][half * 2 + 1] + bv.y;
                asm volatile("red.global.add.v2.f32 [%0], {%1, %2};"
                    :: "l"(op + ncol), "f"(vx), "f"(vy) : "memory");
            }
        }
    }
}

// ---------------- GRU GEMM: 64 rows/CTA, 256 threads, 2 CTA/SM ----------------
__global__ void __launch_bounds__(256, 2) gru_tc(
    const float* __restrict__ A, int which,
    const float* __restrict__ bias, float* __restrict__ C)
{
    extern __shared__ char smem[];
    unsigned sb = smem_u32(smem);
    unsigned* Ahw = (unsigned*)smem;
    unsigned* Alw = Ahw + OFF_ALO_B / 4;
    unsigned bar = sb + OFF_BAR_B;

    int tid = threadIdx.x, lane = tid & 31, wid = tid >> 5;
    int wm = wid >> 2, wn = wid & 3;
    int row0 = blockIdx.x * 64;
    int ny = blockIdx.y, col0 = ny * 256;

    unsigned aHi0 = sb + (wm * 32 + (lane & 15)) * (AW_PITCH * 4) + (lane >> 4) * 16;
    unsigned wOff = b_thread_off(wn, lane);

    if (tid == 0) {
        MB_INIT(bar + 0, 1);  MB_INIT(bar + 8, 1);
        MB_INIT(bar + 16, 8); MB_INIT(bar + 24, 8);
    }
    __syncthreads();

    if (tid == 0) {
#pragma unroll
        for (int g = 0; g < 2; ++g) {
            MB_EXPECT(bar + 8 * g, 16384);
            bulk_g2s(sb + OFF_W_B + g * 16384, &g_gwt[which][ny][g][0][0], 16384, bar + 8 * g);
        }
    }

    {
        int r = tid >> 2, q = tid & 3;
        int rg = row0 + r;
        if (which == 1) {
            size_t grow = (size_t)rg * 128;
            const unsigned* ghi = g_hhi + grow + q * 32;
            const unsigned* glo = g_hlo + grow + q * 32;
            unsigned dh = sb + (r * AW_PITCH + q * 32) * 4;
            unsigned dl = dh + OFF_ALO_B;
#pragma unroll
            for (int i = 0; i < 8; ++i) {
                CP16(dh + 16 * i, ghi + 4 * i);
                CP16(dl + 16 * i, glo + 4 * i);
            }
            CP_COMMIT(); CP_WAIT0();
        } else {
            const float4* sp = (const float4*)(A + (size_t)rg * DD) + q * 16;
            unsigned* dh = Ahw + r * AW_PITCH + q * 32;
            unsigned* dl = Alw + r * AW_PITCH + q * 32;
#pragma unroll
            for (int i = 0; i < 16; ++i) {
                float4 v = sp[i];
                float h0 = __bfloat162float(__float2bfloat16(v.x));
                float h1 = __bfloat162float(__float2bfloat16(v.y));
                float h2 = __bfloat162float(__float2bfloat16(v.z));
                float h3 = __bfloat162float(__float2bfloat16(v.w));
                dh[2 * i]     = pack2(h0, h1);
                dh[2 * i + 1] = pack2(h2, h3);
                dl[2 * i]     = pack2(v.x - h0, v.y - h1);
                dl[2 * i + 1] = pack2(v.z - h2, v.w - h3);
            }
        }
    }
    __syncthreads();

    float acc[2][8][4];
#pragma unroll
    for (int mt = 0; mt < 2; ++mt)
#pragma unroll
        for (int ng = 0; ng < 8; ++ng)
#pragma unroll
            for (int i = 0; i < 4; ++i) acc[mt][ng][i] = 0.f;

    int fph[2] = {0, 0}, eph[2] = {0, 0};
    for (int kc = 0; kc < 16; ++kc) {
        int buf = kc & 1;
        MB_WAIT(bar + 8 * buf, fph[buf]); fph[buf] ^= 1;
        hmma_chunk16(aHi0 + kc * 32, aHi0 + kc * 32 + OFF_ALO_B,
                     sb + OFF_W_B + buf * 16384 + wOff, acc);
        if (lane == 0) MB_ARRIVE(bar + 16 + 8 * buf);
        if (tid == 0 && kc < 14) {
            MB_WAIT(bar + 16 + 8 * buf, eph[buf]); eph[buf] ^= 1;
            MB_EXPECT(bar + 8 * buf, 16384);
            bulk_g2s(sb + OFF_W_B + buf * 16384, &g_gwt[which][ny][kc + 2][0][0], 16384, bar + 8 * buf);
        }
    }

#pragma unroll
    for (int mt = 0; mt < 2; ++mt) {
#pragma unroll
        for (int half = 0; half < 2; ++half) {
            int row = row0 + wm * 32 + mt * 16 + (lane >> 2) + half * 8;
            float* cp = C + (size_t)row * 768 + col0;
#pragma unroll
            for (int nf = 0; nf < 8; ++nf) {
                int ncol = wn * 64 + nf * 8 + (lane & 3) * 2;
                float2 bv = *(const float2*)(bias + col0 + ncol);
                float2 v;
                v.x = acc[mt][nf][half * 2 + 0] + bv.x;
                v.y = acc[mt][nf][half * 2 + 1] + bv.y;
                *(float2*)(cp + ncol) = v;
            }
        }
    }
}

// ---------------- GRU gates + h split refresh ----------------
__global__ void gru_gate2(const float* __restrict__ gi, const float* __restrict__ gh) {
    size_t i2 = (size_t)blockIdx.x * 256 + threadIdx.x;
    size_t row = i2 >> 7;
    int d = (int)(i2 & 127) * 2;
    const float* gir = gi + row * 768;
    const float* ghr = gh + row * 768;
    float2 ir = *(const float2*)(gir + d);
    float2 iz = *(const float2*)(gir + 256 + d);
    float2 in2 = *(const float2*)(gir + 512 + d);
    float2 hr = *(const float2*)(ghr + d);
    float2 hz = *(const float2*)(ghr + 256 + d);
    float2 hn = *(const float2*)(ghr + 512 + d);
    float2 hv = ((const float2*)g_h)[i2];
    float r0 = 1.f / (1.f + expf(-(ir.x + hr.x)));
    float r1 = 1.f / (1.f + expf(-(ir.y + hr.y)));
    float z0 = 1.f / (1.f + expf(-(iz.x + hz.x)));
    float z1 = 1.f / (1.f + expf(-(iz.y + hz.y)));
    float n0 = tanhf(in2.x + r0 * hn.x);
    float n1 = tanhf(in2.y + r1 * hn.y);
    float h0 = (1.f - z0) * n0 + z0 * hv.x;
    float h1 = (1.f - z1) * n1 + z1 * hv.y;
    ((float2*)g_h)[i2] = make_float2(h0, h1);
    float e0 = __bfloat162float(__float2bfloat16(h0));
    float e1 = __bfloat162float(__float2bfloat16(h1));
    g_hhi[i2] = pack2(e0, e1);
    g_hlo[i2] = pack2(h0 - e0, h1 - e1);
}

// ---------------- node sum + head ----------------
__global__ void node_sum() {
    int b = blockIdx.x, chunk = blockIdx.y;
    int d = threadIdx.x;
    const float* base = g_h + ((size_t)b * NN + chunk * 250) * DD + d;
    float acc = 0.f;
    for (int n = 0; n < 250; ++n) acc += base[(size_t)n * DD];
    atomicAdd(&g_s[b * DD + d], acc);
}

__global__ void head_kernel(const float* __restrict__ ptype,
                            const float* __restrict__ fc1w, const float* __restrict__ fc1b,
                            const float* __restrict__ fc2w, const float* __restrict__ fc2b,
                            const float* __restrict__ fc3w, const float* __restrict__ fc3b,
                            float* __restrict__ out)
{
    int b = blockIdx.x, tid = threadIdx.x;
    __shared__ float xs[257];
    __shared__ float red[256];
    __shared__ float a1[HID], a2[HID];

    float sv = g_s[b * DD + tid];
    float l = logf(sv);
    if (isnan(l)) l = 0.f;
    l = fmaxf(l, 0.f);
    float fm = isinf(l) ? -INFINITY : l;
    red[tid] = fm;
    __syncthreads();
    for (int off = 128; off > 0; off >>= 1) {
        if (tid < off) red[tid] = fmaxf(red[tid], red[tid + off]);
        __syncthreads();
    }
    float fmax = red[0];
    if (isinf(l)) l = fmax;
    xs[tid] = l;
    if (tid == 0) xs[256] = ptype[b];
    __syncthreads();

    if (tid < HID) {
        float acc = fc1b[tid];
        for (int k = 0; k < 257; ++k) acc += fc1w[tid * 257 + k] * xs[k];
        a1[tid] = acc > 0.f ? acc : 0.01f * acc;
    }
    __syncthreads();
    if (tid < HID) {
        float acc = fc2b[tid];
        for (int k = 0; k < HID; ++k) acc += fc2w[tid * HID + k] * a1[k];
        a2[tid] = acc > 0.f ? acc : 0.01f * acc;
    }
    __syncthreads();
    if (tid < OUTD) {
        float acc = fc3b[tid];
        for (int k = 0; k < HID; ++k) acc += fc3w[tid * HID + k] * a2[k];
        out[b * OUTD + tid] = acc;
    }
}

// ---------------- launch ----------------
extern "C" void kernel_launch(void* const* d_in, const int* in_sizes, int n_in,
                              void* d_out, int out_size) {
    const float* nodes = (const float*)d_in[0];
    const int*   edges = (const int*)  d_in[1];
    const float* ptype = (const float*)d_in[2];
    const float* w_ih  = (const float*)d_in[3];
    const float* w_hh  = (const float*)d_in[4];
    const float* b_ih  = (const float*)d_in[5];
    const float* b_hh  = (const float*)d_in[6];
    const float* ew1   = (const float*)d_in[7];
    const float* eb1   = (const float*)d_in[8];
    const float* ew2   = (const float*)d_in[9];
    const float* eb2   = (const float*)d_in[10];
    const float* fc1w  = (const float*)d_in[11];
    const float* fc1b  = (const float*)d_in[12];
    const float* fc2w  = (const float*)d_in[13];
    const float* fc2b  = (const float*)d_in[14];
    const float* fc3w  = (const float*)d_in[15];
    const float* fc3b  = (const float*)d_in[16];
    float* out = (float*)d_out;

    float *p_h, *p_inc, *p_gi, *p_gh, *p_s;
    cudaGetSymbolAddress((void**)&p_h,   g_h);
    cudaGetSymbolAddress((void**)&p_inc, g_inc);
    cudaGetSymbolAddress((void**)&p_gi,  g_gi);
    cudaGetSymbolAddress((void**)&p_gh,  g_gh);
    cudaGetSymbolAddress((void**)&p_s,   g_s);

    cudaFuncSetAttribute(edge_tc, cudaFuncAttributeMaxDynamicSharedMemorySize, TSMEM);
    cudaFuncSetAttribute(gru_tc,  cudaFuncAttributeMaxDynamicSharedMemorySize, TSMEM);

    const int n4_state = MROWS * DD / 4;

    split_init<<<MROWS * 128 / 256, 256>>>(nodes);
    prep_weights<<<1536, 256>>>(ew1, ew2, w_ih, w_hh);

    for (int j = 0; j < NPASS; ++j) {
        zero4<<<(n4_state + 255) / 256, 256>>>((float4*)p_inc, n4_state);
        edge_tc<<<dim3(EE / 64, BB, SS), 256, TSMEM>>>(edges, eb1, eb2);
        gru_tc<<<dim3(MROWS / 64, 3), 256, TSMEM>>>(p_inc, 0, b_ih, p_gi);
        gru_tc<<<dim3(MROWS / 64, 3), 256, TSMEM>>>(p_h,   1, b_hh, p_gh);
        gru_gate2<<<MROWS * 128 / 256, 256>>>(p_gi, p_gh);
    }

    zero4<<<1, 256>>>((float4*)p_s, BB * DD / 4);
    node_sum<<<dim3(BB, 40), 256>>>();
    head_kernel<<<BB, 256>>>(ptype, fc1w, fc1b, fc2w, fc2b, fc3w, fc3b, out);
}